// round 8
// baseline (speedup 1.0000x reference)
#include <cuda_runtime.h>
#include <cstdint>

#define NN 100000
#define NE 600000
#define NET 3
#define NL 3
#define DD 128
#define EPS 1e-5f
#define NROWS (NET * NN)
#define SCAN_BLK 293

// ---------------- static device scratch (device-code access ONLY) ----------------
__device__ float d_accA[(size_t)NN * DD];
__device__ float d_accB[(size_t)NN * DD];
__device__ float d_invdeg[NROWS];
__device__ float d_stats3[NL * 2 * DD];
__device__ float d_Wt[(size_t)NL * NET * 2 * DD * DD];  // W^T tf32: [l][e][sel][n][kk]
__device__ int   d_cnt[NROWS];
__device__ int   d_rowoff[NROWS + 1];
__device__ int   d_bsums[512];
__device__ int   d_esrc[NET * NE];

// ======================= prep: CSR build =======================

__global__ void zero_cnt_kernel() {
    int i = blockIdx.x * blockDim.x + threadIdx.x;
    if (i < NROWS) d_cnt[i] = 0;
    if (i < NL * 2 * DD) d_stats3[i] = 0.f;
}
__global__ void deg_count_kernel(const int* __restrict__ dst) {
    int idx = blockIdx.x * blockDim.x + threadIdx.x;
    if (idx >= NET * NE) return;
    int k = idx / NE;
    atomicAdd(&d_cnt[k * NN + __ldg(dst + idx)], 1);
}
__global__ void scan1_kernel() {
    int base = blockIdx.x * 1024;
    int t = threadIdx.x;
    int sum = 0;
#pragma unroll
    for (int j = 0; j < 4; j++) {
        int i = base + t * 4 + j;
        if (i < NROWS) sum += d_cnt[i];
    }
#pragma unroll
    for (int o = 16; o; o >>= 1) sum += __shfl_down_sync(0xFFFFFFFFu, sum, o);
    __shared__ int ws[8];
    if ((t & 31) == 0) ws[t >> 5] = sum;
    __syncthreads();
    if (t == 0) {
        int v = 0;
#pragma unroll
        for (int i = 0; i < 8; i++) v += ws[i];
        d_bsums[blockIdx.x] = v;
    }
}
__global__ void scan2_kernel() {
    __shared__ int s[512];
    int t = threadIdx.x;
    int orig = (t < SCAN_BLK) ? d_bsums[t] : 0;
    s[t] = orig;
    __syncthreads();
#pragma unroll
    for (int o = 1; o < 512; o <<= 1) {
        int v = (t >= o) ? s[t - o] : 0;
        __syncthreads();
        s[t] += v;
        __syncthreads();
    }
    if (t < SCAN_BLK) d_bsums[t] = s[t] - orig;
}
__global__ void scan3_kernel() {
    int base = blockIdx.x * 1024;
    int t = threadIdx.x, lane = t & 31, warp = t >> 5;
    int vals[4];
    int tsum = 0;
#pragma unroll
    for (int j = 0; j < 4; j++) {
        int i = base + t * 4 + j;
        vals[j] = (i < NROWS) ? d_cnt[i] : 0;
        tsum += vals[j];
    }
    int inc = tsum;
#pragma unroll
    for (int o = 1; o < 32; o <<= 1) {
        int v = __shfl_up_sync(0xFFFFFFFFu, inc, o);
        if (lane >= o) inc += v;
    }
    int texcl = inc - tsum;
    __shared__ int wsum[8];
    if (lane == 31) wsum[warp] = inc;
    __syncthreads();
    __shared__ int woff[8];
    if (t == 0) {
        int a = 0;
#pragma unroll
        for (int i = 0; i < 8; i++) { woff[i] = a; a += wsum[i]; }
    }
    __syncthreads();
    int run = d_bsums[blockIdx.x] + woff[warp] + texcl;
#pragma unroll
    for (int j = 0; j < 4; j++) {
        int i = base + t * 4 + j;
        if (i < NROWS) {
            d_rowoff[i] = run;
            d_invdeg[i] = 1.0f / fmaxf((float)vals[j], 1.0f);
            d_cnt[i] = 0;
            run += vals[j];
        }
    }
    if (blockIdx.x == 0 && t == 0) d_rowoff[NROWS] = NET * NE;
}
__global__ void permute_kernel(const int* __restrict__ src, const int* __restrict__ dst) {
    int idx = blockIdx.x * blockDim.x + threadIdx.x;
    if (idx >= NET * NE) return;
    int k = idx / NE;
    int g = k * NN + __ldg(dst + idx);
    int pos = d_rowoff[g] + atomicAdd(&d_cnt[g], 1);
    d_esrc[pos] = __ldg(src + idx);
}

__device__ __forceinline__ uint32_t f2tf32(float x) {
    uint32_t r;
    asm("cvt.rna.tf32.f32 %0, %1;" : "=r"(r) : "f"(x));
    return r;
}

// W^T + tf32; layer-2 self slot 0 holds merged sum(Ws_e)
__global__ void wt_prep_kernel(const float* __restrict__ Ws, const float* __restrict__ Wn) {
    int i = blockIdx.x * blockDim.x + threadIdx.x;
    if (i >= NL * NET * 2 * DD * DD) return;
    int kk = i & 127;
    int n = (i >> 7) & 127;
    int sel = (i >> 14) & 1;
    int m = i >> 15;
    float v;
    if (m == 2 * NET && sel == 0) {  // layer 2, etype 0, self -> merged
        v = __ldg(Ws + (size_t)6 * 16384 + kk * DD + n)
          + __ldg(Ws + (size_t)7 * 16384 + kk * DD + n)
          + __ldg(Ws + (size_t)8 * 16384 + kk * DD + n);
    } else {
        v = __ldg((sel ? Wn : Ws) + (size_t)m * 16384 + kk * DD + n);
    }
    d_Wt[i] = __uint_as_float(f2tf32(v));
}

// ======================= fused gather + GEMM + BN =======================
// Per CTA (128 rows): H tile = BN(prev acc) or x; per etype: gather neigh into smem,
// MMA self+neigh, fold bias(+relu). Epilogue: store acc + BN stats.

#define HSTRIDE 132
#define HSZ (128 * HSTRIDE)     // floats
#define BSTR 36
#define BTILE (128 * BSTR)      // floats
#define SM_FLOATS (2 * HSZ + 2 * BTILE + 256)
#define SMEM_BYTES (SM_FLOATS * 4)   // 173,056 B

__device__ __forceinline__ void ldsm4(uint32_t* r, uint32_t addr) {
    asm volatile("ldmatrix.sync.aligned.m8n8.x4.shared.b16 {%0,%1,%2,%3}, [%4];"
                 : "=r"(r[0]), "=r"(r[1]), "=r"(r[2]), "=r"(r[3]) : "r"(addr));
}
__device__ __forceinline__ void mma8(float* c, const uint32_t* a, uint32_t b0, uint32_t b1) {
    asm volatile("mma.sync.aligned.m16n8k8.row.col.f32.tf32.tf32.f32 "
                 "{%0,%1,%2,%3}, {%4,%5,%6,%7}, {%8,%9}, {%0,%1,%2,%3};"
                 : "+f"(c[0]), "+f"(c[1]), "+f"(c[2]), "+f"(c[3])
                 : "r"(a[0]), "r"(a[1]), "r"(a[2]), "r"(a[3]), "r"(b0), "r"(b1));
}
__device__ __forceinline__ void ldgB(float4* rb, const float* __restrict__ W,
                                     int koff, int tid) {
#pragma unroll
    for (int t = 0; t < 4; t++) {
        int c = tid + t * 256;
        rb[t] = __ldg(reinterpret_cast<const float4*>(W + (size_t)(c >> 3) * DD + koff) + (c & 7));
    }
}
__device__ __forceinline__ void stsB(float* Bs, const float4* rb, int tid) {
#pragma unroll
    for (int t = 0; t < 4; t++) {
        int c = tid + t * 256;
        *reinterpret_cast<float4*>(Bs + (c >> 3) * BSTR + (c & 7) * 4) = rb[t];
    }
}

__global__ void __launch_bounds__(256)
gemm_fused_kernel(const float* __restrict__ x, int use_x, int layer,
                  const float* __restrict__ bias /*[NET][128]*/, int do_relu,
                  const float* __restrict__ gprev, const float* __restrict__ bprev) {
    extern __shared__ float sm[];
    float* Hs = sm;
    float* NBs = sm + HSZ;
    float* Bb[2] = { sm + 2 * HSZ, sm + 2 * HSZ + BTILE };
    float* scale_s = sm + 2 * HSZ + 2 * BTILE;
    float* shift_s = scale_s + DD;
    uint32_t smb = (uint32_t)__cvta_generic_to_shared(sm);
    uint32_t h_u = smb, nb_u = smb + HSZ * 4;
    uint32_t bb_u[2] = { smb + 2 * HSZ * 4, smb + (2 * HSZ + BTILE) * 4 };

    const float* accr = (layer & 1) ? d_accA : d_accB;   // input (prev layer); unused for l=0
    float* accw = (layer & 1) ? d_accB : d_accA;          // output
    const float* hin = use_x ? x : accr;
    const float* Wl = d_Wt + (size_t)layer * NET * 2 * DD * DD;
    float* stats = d_stats3 + layer * 2 * DD;

    int tid = threadIdx.x, lane = tid & 31, wid = tid >> 5;
    int wm = wid & 3, wn = wid >> 2;
    int m0 = blockIdx.x * 128;

    // BN affine consts of previous layer
    if (!use_x && tid < DD) {
        const float* st = d_stats3 + (layer - 1) * 2 * DD;
        float mu = st[tid] * (1.0f / NN);
        float var = st[DD + tid] * (1.0f / NN) - mu * mu;
        float sc = __ldg(gprev + tid) * rsqrtf(var + EPS);
        scale_s[tid] = sc;
        shift_s[tid] = __ldg(bprev + tid) - mu * sc;
    }
    __syncthreads();
    float4 sc4 = make_float4(1.f, 1.f, 1.f, 1.f);
    float4 sh4 = make_float4(0.f, 0.f, 0.f, 0.f);
    if (!use_x) {
        sc4 = *reinterpret_cast<float4*>(&scale_s[lane * 4]);
        sh4 = *reinterpret_cast<float4*>(&shift_s[lane * 4]);
    }

    // ---- load H tile: BN(prev acc) or x, tf32-rounded ----
#pragma unroll
    for (int t = 0; t < 16; t++) {
        int c = tid + t * 256;
        int row = c >> 5;             // q == lane
        int gr = m0 + row;
        float4 v = make_float4(0.f, 0.f, 0.f, 0.f);
        if (gr < NN) {
            v = __ldg(reinterpret_cast<const float4*>(hin + (size_t)gr * DD) + lane);
            if (!use_x) {
                v.x = fmaf(v.x, sc4.x, sh4.x); v.y = fmaf(v.y, sc4.y, sh4.y);
                v.z = fmaf(v.z, sc4.z, sh4.z); v.w = fmaf(v.w, sc4.w, sh4.w);
            }
        }
        uint4 u;
        u.x = f2tf32(v.x); u.y = f2tf32(v.y); u.z = f2tf32(v.z); u.w = f2tf32(v.w);
        *reinterpret_cast<uint4*>(Hs + row * HSTRIDE + lane * 4) = u;
    }

    // ldmatrix lane offsets
    uint32_t aoffb[2];
#pragma unroll
    for (int mf = 0; mf < 2; mf++)
        aoffb[mf] = ((wm * 32 + mf * 16 + (lane & 15)) * HSTRIDE + (lane >> 4) * 4) * 4;
    uint32_t boffb[4];
#pragma unroll
    for (int nf2 = 0; nf2 < 4; nf2++) {
        int n = wn * 64 + nf2 * 16 + (lane & 7) + ((lane >> 4) << 3);
        boffb[nf2] = (n * BSTR + ((lane >> 3) & 1) * 4) * 4;
    }

    float facc[2][8][4], acc[2][8][4];
#pragma unroll
    for (int i = 0; i < 2; i++)
#pragma unroll
        for (int j = 0; j < 8; j++)
#pragma unroll
            for (int e = 0; e < 4; e++) { facc[i][j][e] = 0.f; acc[i][j][e] = 0.f; }

    float4 rb[4];
    ldgB(rb, Wl + (layer == 2 ? 0 : 0), 0, tid);   // group 0 first chunk (self slot 0)

    for (int g = 0; g < NET; g++) {
        const bool has_self = (layer < 2) || (g == 0);
        const int ns = has_self ? 8 : 4;

        __syncthreads();   // all warps done reading NBs / B bufs from prior group

        // ---- gather etype g into NBs (B prefetch LDGs in flight) ----
#pragma unroll 1
        for (int i = 0; i < 16; i++) {
            int r = wid + i * 8;
            int row = m0 + r;
            float4 a = make_float4(0.f, 0.f, 0.f, 0.f);
            if (row < NN) {
                int grow = g * NN + row;
                int o0 = __ldg(&d_rowoff[grow]);
                int o1 = __ldg(&d_rowoff[grow + 1]);
                if (o1 > o0) {
                    int s = __ldg(&d_esrc[o0]);
                    for (int e = o0; e < o1; e++) {
                        int sn = (e + 1 < o1) ? __ldg(&d_esrc[e + 1]) : 0;
                        float4 v = __ldg(reinterpret_cast<const float4*>(hin + (size_t)s * DD) + lane);
                        a.x += v.x; a.y += v.y; a.z += v.z; a.w += v.w;
                        s = sn;
                    }
                    float iv = d_invdeg[grow];
                    a.x *= iv; a.y *= iv; a.z *= iv; a.w *= iv;
                    if (!use_x) {
                        a.x = fmaf(a.x, sc4.x, sh4.x); a.y = fmaf(a.y, sc4.y, sh4.y);
                        a.z = fmaf(a.z, sc4.z, sh4.z); a.w = fmaf(a.w, sc4.w, sh4.w);
                    }
                }
            }
            uint4 u;
            u.x = f2tf32(a.x); u.y = f2tf32(a.y); u.z = f2tf32(a.z); u.w = f2tf32(a.w);
            *reinterpret_cast<uint4*>(NBs + r * HSTRIDE + lane * 4) = u;
        }
        __syncthreads();   // NB + H visible
        stsB(Bb[0], rb, tid);
        __syncthreads();

        for (int s = 0; s < ns; s++) {
            const bool last = (s == ns - 1);
            if (!last) {
                int sel = has_self ? (s + 1 >= 4) : 1;
                ldgB(rb, Wl + (size_t)(g * 2 + sel) * 16384, ((s + 1) & 3) * 32, tid);
            } else if (g < NET - 1) {
                int nsel = (layer < 2) || (g + 1 == 0) ? 0 : 1;  // next group: self if it has one
                ldgB(rb, Wl + (size_t)((g + 1) * 2 + nsel) * 16384, 0, tid);
            }
            // ---- compute ----
            uint32_t abase = ((has_self && s < 4) ? h_u : nb_u) + (s & 3) * 128;
            uint32_t bbase = bb_u[s & 1];
#pragma unroll
            for (int ks = 0; ks < 4; ks++) {
                uint32_t af[2][4];
                ldsm4(af[0], abase + aoffb[0] + ks * 32);
                ldsm4(af[1], abase + aoffb[1] + ks * 32);
                uint32_t bf[4][4];
#pragma unroll
                for (int nf2 = 0; nf2 < 4; nf2++)
                    ldsm4(bf[nf2], bbase + boffb[nf2] + ks * 32);
#pragma unroll
                for (int mf = 0; mf < 2; mf++)
#pragma unroll
                    for (int nf = 0; nf < 8; nf++) {
                        int q = (nf & 1) * 2;
                        mma8(acc[mf][nf], af[mf], bf[nf >> 1][q], bf[nf >> 1][q + 1]);
                    }
            }
            if (!last) {
                __syncthreads();
                stsB(Bb[(s + 1) & 1], rb, tid);
                __syncthreads();
            }
        }

        // ---- fold group: bias (+relu) into facc ----
        const float* be = bias + g * DD;
#pragma unroll
        for (int nf = 0; nf < 8; nf++) {
            int n = wn * 64 + nf * 8 + ((lane & 3) << 1);
            float b0 = __ldg(be + n), b1 = __ldg(be + n + 1);
#pragma unroll
            for (int mf = 0; mf < 2; mf++) {
                float v0 = acc[mf][nf][0] + b0, v1 = acc[mf][nf][1] + b1;
                float v2 = acc[mf][nf][2] + b0, v3 = acc[mf][nf][3] + b1;
                if (do_relu) {
                    v0 = fmaxf(v0, 0.f); v1 = fmaxf(v1, 0.f);
                    v2 = fmaxf(v2, 0.f); v3 = fmaxf(v3, 0.f);
                }
                facc[mf][nf][0] += v0; facc[mf][nf][1] += v1;
                facc[mf][nf][2] += v2; facc[mf][nf][3] += v3;
                acc[mf][nf][0] = 0.f; acc[mf][nf][1] = 0.f;
                acc[mf][nf][2] = 0.f; acc[mf][nf][3] = 0.f;
            }
        }
    }

    // ---- epilogue: store + BN column stats ----
    int r0 = m0 + wm * 32 + (lane >> 2);
    int rr[2] = { r0, r0 + 16 };
#pragma unroll
    for (int nf = 0; nf < 8; nf++) {
        int n = wn * 64 + nf * 8 + ((lane & 3) << 1);
        float s0 = 0.f, s1 = 0.f, q0 = 0.f, q1 = 0.f;
#pragma unroll
        for (int mf = 0; mf < 2; mf++) {
            int r = rr[mf];
            float v0 = facc[mf][nf][0], v1 = facc[mf][nf][1];
            float v2 = facc[mf][nf][2], v3 = facc[mf][nf][3];
            if (r < NN) {
                *reinterpret_cast<float2*>(accw + (size_t)r * DD + n) = make_float2(v0, v1);
                s0 += v0; s1 += v1;
                q0 = fmaf(v0, v0, q0); q1 = fmaf(v1, v1, q1);
            }
            if (r + 8 < NN) {
                *reinterpret_cast<float2*>(accw + (size_t)(r + 8) * DD + n) = make_float2(v2, v3);
                s0 += v2; s1 += v3;
                q0 = fmaf(v2, v2, q0); q1 = fmaf(v3, v3, q1);
            }
        }
#pragma unroll
        for (int o = 4; o < 32; o <<= 1) {
            s0 += __shfl_xor_sync(0xFFFFFFFFu, s0, o);
            s1 += __shfl_xor_sync(0xFFFFFFFFu, s1, o);
            q0 += __shfl_xor_sync(0xFFFFFFFFu, q0, o);
            q1 += __shfl_xor_sync(0xFFFFFFFFu, q1, o);
        }
        if (lane < 4) {
            atomicAdd(stats + n, s0);
            atomicAdd(stats + n + 1, s1);
            atomicAdd(stats + DD + n, q0);
            atomicAdd(stats + DD + n + 1, q1);
        }
    }
}

// ======================= final BatchNorm (layer 2 -> out) =======================

__global__ void bn_final_kernel(const float* __restrict__ gamma,
                                const float* __restrict__ beta,
                                float* __restrict__ outp) {
    __shared__ float scale_s[DD];
    __shared__ float shift_s[DD];
    if (threadIdx.x < DD) {
        int c = threadIdx.x;
        const float* st = d_stats3 + 2 * 2 * DD;
        float mu = st[c] * (1.0f / NN);
        float var = st[DD + c] * (1.0f / NN) - mu * mu;
        float sc = __ldg(gamma + c) * rsqrtf(var + EPS);
        scale_s[c] = sc;
        shift_s[c] = __ldg(beta + c) - mu * sc;
    }
    __syncthreads();
    size_t i = (size_t)blockIdx.x * blockDim.x + threadIdx.x;
    if (i >= (size_t)NN * DD / 4) return;
    int col = (int)((i * 4) & (DD - 1));
    float4 v = reinterpret_cast<const float4*>(d_accA)[i];  // layer 2 writes A
    float4 o;
    o.x = v.x * scale_s[col + 0] + shift_s[col + 0];
    o.y = v.y * scale_s[col + 1] + shift_s[col + 1];
    o.z = v.z * scale_s[col + 2] + shift_s[col + 2];
    o.w = v.w * scale_s[col + 3] + shift_s[col + 3];
    reinterpret_cast<float4*>(outp)[i] = o;
}

// ======================= launch =======================

extern "C" void kernel_launch(void* const* d_in, const int* in_sizes, int n_in,
                              void* d_out, int out_size) {
    const float* x     = (const float*)d_in[0];
    const int*   src   = (const int*)d_in[1];
    const int*   dst   = (const int*)d_in[2];
    const float* Ws    = (const float*)d_in[3];
    const float* Wn    = (const float*)d_in[4];
    const float* bias  = (const float*)d_in[5];
    const float* gamma = (const float*)d_in[6];
    const float* beta  = (const float*)d_in[7];
    float* out = (float*)d_out;

    cudaFuncSetAttribute(gemm_fused_kernel,
                         cudaFuncAttributeMaxDynamicSharedMemorySize, SMEM_BYTES);

    {
        int n = NL * NET * 2 * DD * DD;
        wt_prep_kernel<<<(n + 255) / 256, 256>>>(Ws, Wn);
    }
    {
        zero_cnt_kernel<<<(NROWS + 255) / 256, 256>>>();
        int ne = NET * NE;
        deg_count_kernel<<<(ne + 255) / 256, 256>>>(dst);
        scan1_kernel<<<SCAN_BLK, 256>>>();
        scan2_kernel<<<1, 512>>>();
        scan3_kernel<<<SCAN_BLK, 256>>>();
        permute_kernel<<<(ne + 255) / 256, 256>>>(src, dst);
    }

    const int gemm_blocks = (NN + 127) / 128;   // 782
    const int bn4_blocks = (NN * DD / 4 + 255) / 256;

    for (int l = 0; l < NL; l++) {
        int pl = (l > 0) ? (l - 1) : 0;
        gemm_fused_kernel<<<gemm_blocks, 256, SMEM_BYTES>>>(
            x, (l == 0), l, bias + (size_t)l * NET * DD, (l < NL - 1),
            gamma + (size_t)pl * DD, beta + (size_t)pl * DD);
    }
    bn_final_kernel<<<bn4_blocks, 256>>>(gamma + 2 * DD, beta + 2 * DD, out);
}

// round 9
// speedup vs baseline: 1.0140x; 1.0140x over previous
#include <cuda_runtime.h>
#include <cstdint>

#define NN 100000
#define NE 600000
#define NET 3
#define NL 3
#define DD 128
#define EPS 1e-5f
#define NROWS (NET * NN)
#define SCAN_BLK 293

// ---------------- static device scratch (device-code access ONLY) ----------------
__device__ float d_accA[(size_t)NN * DD];
__device__ float d_accB[(size_t)NN * DD];
__device__ float d_neigh[(size_t)NET * NN * DD];
__device__ float d_invdeg[NROWS];
__device__ float d_stats3[NL * 2 * DD];
__device__ float d_Wt[(size_t)NL * NET * 2 * DD * DD];  // W^T tf32: [l][e][sel][n][kk]
__device__ int   d_cnt[NROWS];
__device__ int   d_rowoff[NROWS + 1];
__device__ int   d_bsums[512];
__device__ int   d_esrc[NET * NE];

// ======================= prep: CSR build =======================

__global__ void zero_cnt_kernel() {
    int i = blockIdx.x * blockDim.x + threadIdx.x;
    if (i < NROWS) d_cnt[i] = 0;
    if (i < NL * 2 * DD) d_stats3[i] = 0.f;
}
__global__ void deg_count_kernel(const int* __restrict__ dst) {
    int idx = blockIdx.x * blockDim.x + threadIdx.x;
    if (idx >= NET * NE) return;
    int k = idx / NE;
    atomicAdd(&d_cnt[k * NN + __ldg(dst + idx)], 1);
}
__global__ void scan1_kernel() {
    int base = blockIdx.x * 1024;
    int t = threadIdx.x;
    int sum = 0;
#pragma unroll
    for (int j = 0; j < 4; j++) {
        int i = base + t * 4 + j;
        if (i < NROWS) sum += d_cnt[i];
    }
#pragma unroll
    for (int o = 16; o; o >>= 1) sum += __shfl_down_sync(0xFFFFFFFFu, sum, o);
    __shared__ int ws[8];
    if ((t & 31) == 0) ws[t >> 5] = sum;
    __syncthreads();
    if (t == 0) {
        int v = 0;
#pragma unroll
        for (int i = 0; i < 8; i++) v += ws[i];
        d_bsums[blockIdx.x] = v;
    }
}
__global__ void scan2_kernel() {
    __shared__ int s[512];
    int t = threadIdx.x;
    int orig = (t < SCAN_BLK) ? d_bsums[t] : 0;
    s[t] = orig;
    __syncthreads();
#pragma unroll
    for (int o = 1; o < 512; o <<= 1) {
        int v = (t >= o) ? s[t - o] : 0;
        __syncthreads();
        s[t] += v;
        __syncthreads();
    }
    if (t < SCAN_BLK) d_bsums[t] = s[t] - orig;
}
__global__ void scan3_kernel() {
    int base = blockIdx.x * 1024;
    int t = threadIdx.x, lane = t & 31, warp = t >> 5;
    int vals[4];
    int tsum = 0;
#pragma unroll
    for (int j = 0; j < 4; j++) {
        int i = base + t * 4 + j;
        vals[j] = (i < NROWS) ? d_cnt[i] : 0;
        tsum += vals[j];
    }
    int inc = tsum;
#pragma unroll
    for (int o = 1; o < 32; o <<= 1) {
        int v = __shfl_up_sync(0xFFFFFFFFu, inc, o);
        if (lane >= o) inc += v;
    }
    int texcl = inc - tsum;
    __shared__ int wsum[8];
    if (lane == 31) wsum[warp] = inc;
    __syncthreads();
    __shared__ int woff[8];
    if (t == 0) {
        int a = 0;
#pragma unroll
        for (int i = 0; i < 8; i++) { woff[i] = a; a += wsum[i]; }
    }
    __syncthreads();
    int run = d_bsums[blockIdx.x] + woff[warp] + texcl;
#pragma unroll
    for (int j = 0; j < 4; j++) {
        int i = base + t * 4 + j;
        if (i < NROWS) {
            d_rowoff[i] = run;
            d_invdeg[i] = 1.0f / fmaxf((float)vals[j], 1.0f);
            d_cnt[i] = 0;
            run += vals[j];
        }
    }
    if (blockIdx.x == 0 && t == 0) d_rowoff[NROWS] = NET * NE;
}
__global__ void permute_kernel(const int* __restrict__ src, const int* __restrict__ dst) {
    int idx = blockIdx.x * blockDim.x + threadIdx.x;
    if (idx >= NET * NE) return;
    int k = idx / NE;
    int g = k * NN + __ldg(dst + idx);
    int pos = d_rowoff[g] + atomicAdd(&d_cnt[g], 1);
    d_esrc[pos] = __ldg(src + idx);
}

__device__ __forceinline__ uint32_t f2tf32(float x) {
    uint32_t r;
    asm("cvt.rna.tf32.f32 %0, %1;" : "=r"(r) : "f"(x));
    return r;
}

// W^T + tf32; layer-2 slot (e=0,self) holds merged sum_e(Ws_e)
__global__ void wt_prep_kernel(const float* __restrict__ Ws, const float* __restrict__ Wn) {
    int i = blockIdx.x * blockDim.x + threadIdx.x;
    if (i >= NL * NET * 2 * DD * DD) return;
    int kk = i & 127;
    int n = (i >> 7) & 127;
    int sel = (i >> 14) & 1;
    int m = i >> 15;
    float v;
    if (m == 2 * NET && sel == 0) {
        v = __ldg(Ws + (size_t)6 * 16384 + kk * DD + n)
          + __ldg(Ws + (size_t)7 * 16384 + kk * DD + n)
          + __ldg(Ws + (size_t)8 * 16384 + kk * DD + n);
    } else {
        v = __ldg((sel ? Wn : Ws) + (size_t)m * 16384 + kk * DD + n);
    }
    d_Wt[i] = __uint_as_float(f2tf32(v));
}

// ======================= gather (CSR mean, BN-of-prev folded in) =======================
__global__ void gather_kernel(const float* __restrict__ x, int use_x, int layer,
                              const float* __restrict__ gprev, const float* __restrict__ bprev) {
    const float* hin = use_x ? x : ((layer & 1) ? d_accA : d_accB);  // prev layer's output acc
    int w = (blockIdx.x * blockDim.x + threadIdx.x) >> 5;
    int lane = threadIdx.x & 31;
    if (w >= NROWS) return;

    float4 sc4 = make_float4(1.f, 1.f, 1.f, 1.f);
    float4 sh4 = make_float4(0.f, 0.f, 0.f, 0.f);
    if (!use_x) {
        const float* st = d_stats3 + (layer - 1) * 2 * DD;
        float4 s = __ldg(reinterpret_cast<const float4*>(st) + lane);
        float4 q = __ldg(reinterpret_cast<const float4*>(st + DD) + lane);
        float4 gm = __ldg(reinterpret_cast<const float4*>(gprev) + lane);
        float4 bt = __ldg(reinterpret_cast<const float4*>(bprev) + lane);
        float mu0 = s.x / NN, mu1 = s.y / NN, mu2 = s.z / NN, mu3 = s.w / NN;
        sc4.x = gm.x * rsqrtf(q.x / NN - mu0 * mu0 + EPS);
        sc4.y = gm.y * rsqrtf(q.y / NN - mu1 * mu1 + EPS);
        sc4.z = gm.z * rsqrtf(q.z / NN - mu2 * mu2 + EPS);
        sc4.w = gm.w * rsqrtf(q.w / NN - mu3 * mu3 + EPS);
        sh4.x = bt.x - mu0 * sc4.x; sh4.y = bt.y - mu1 * sc4.y;
        sh4.z = bt.z - mu2 * sc4.z; sh4.w = bt.w - mu3 * sc4.w;
    }

    int o0 = __ldg(&d_rowoff[w]);
    int o1 = __ldg(&d_rowoff[w + 1]);
    float4 a = make_float4(0.f, 0.f, 0.f, 0.f);
    if (o1 > o0) {
        int s = __ldg(&d_esrc[o0]);
        for (int e = o0; e < o1; e++) {
            int sn = (e + 1 < o1) ? __ldg(&d_esrc[e + 1]) : 0;
            float4 v = __ldg(reinterpret_cast<const float4*>(hin + (size_t)s * DD) + lane);
            a.x += v.x; a.y += v.y; a.z += v.z; a.w += v.w;
            s = sn;
        }
        float iv = d_invdeg[w];
        a.x *= iv; a.y *= iv; a.z *= iv; a.w *= iv;
        // mean(BN(h)) = sc*mean + sh  (deg>0 only; deg==0 stays exactly 0)
        a.x = fmaf(a.x, sc4.x, sh4.x); a.y = fmaf(a.y, sc4.y, sh4.y);
        a.z = fmaf(a.z, sc4.z, sh4.z); a.w = fmaf(a.w, sc4.w, sh4.w);
    }
    reinterpret_cast<float4*>(d_neigh)[(size_t)w * 32 + lane] = a;
}

// ======================= merged tf32 mma GEMM (fused BN-reduce + BN-of-prev on h) =======================

#define ASTRIDE 36
#define ATILE (128 * ASTRIDE)
#define SMEM_BYTES ((4 * ATILE + 2 * DD) * 4)

__device__ __forceinline__ void ldsm4(uint32_t* r, uint32_t addr) {
    asm volatile("ldmatrix.sync.aligned.m8n8.x4.shared.b16 {%0,%1,%2,%3}, [%4];"
                 : "=r"(r[0]), "=r"(r[1]), "=r"(r[2]), "=r"(r[3]) : "r"(addr));
}
__device__ __forceinline__ void mma8(float* c, const uint32_t* a, uint32_t b0, uint32_t b1) {
    asm volatile("mma.sync.aligned.m16n8k8.row.col.f32.tf32.tf32.f32 "
                 "{%0,%1,%2,%3}, {%4,%5,%6,%7}, {%8,%9}, {%0,%1,%2,%3};"
                 : "+f"(c[0]), "+f"(c[1]), "+f"(c[2]), "+f"(c[3])
                 : "r"(a[0]), "r"(a[1]), "r"(a[2]), "r"(a[3]), "r"(b0), "r"(b1));
}

__device__ __forceinline__ void ldgA(float4* ra, const float* __restrict__ src,
                                     int m0, int koff, int tid, int affine,
                                     const float* __restrict__ scale_s,
                                     const float* __restrict__ shift_s) {
#pragma unroll
    for (int t = 0; t < 4; t++) {
        int c = tid + t * 256;
        int gr = m0 + (c >> 3);
        float4 v = make_float4(0.f, 0.f, 0.f, 0.f);
        if (gr < NN) {
            v = __ldg(reinterpret_cast<const float4*>(src + (size_t)gr * DD + koff) + (c & 7));
            if (affine) {
                int col = koff + (c & 7) * 4;
                float4 sc = *reinterpret_cast<const float4*>(scale_s + col);
                float4 sh = *reinterpret_cast<const float4*>(shift_s + col);
                v.x = fmaf(v.x, sc.x, sh.x); v.y = fmaf(v.y, sc.y, sh.y);
                v.z = fmaf(v.z, sc.z, sh.z); v.w = fmaf(v.w, sc.w, sh.w);
            }
        }
        ra[t] = v;
    }
}
__device__ __forceinline__ void ldgB(float4* rb, const float* __restrict__ W,
                                     int koff, int tid) {
#pragma unroll
    for (int t = 0; t < 4; t++) {
        int c = tid + t * 256;
        rb[t] = __ldg(reinterpret_cast<const float4*>(W + (size_t)(c >> 3) * DD + koff) + (c & 7));
    }
}
__device__ __forceinline__ void stsA(float* As, const float4* ra, int tid) {
#pragma unroll
    for (int t = 0; t < 4; t++) {
        int c = tid + t * 256;
        uint4 u;
        u.x = f2tf32(ra[t].x); u.y = f2tf32(ra[t].y);
        u.z = f2tf32(ra[t].z); u.w = f2tf32(ra[t].w);
        *reinterpret_cast<uint4*>(As + (c >> 3) * ASTRIDE + (c & 7) * 4) = u;
    }
}
__device__ __forceinline__ void stsB(float* Bs, const float4* rb, int tid) {
#pragma unroll
    for (int t = 0; t < 4; t++) {
        int c = tid + t * 256;
        *reinterpret_cast<float4*>(Bs + (c >> 3) * ASTRIDE + (c & 7) * 4) = rb[t];
    }
}

// tile schedule: returns A source, W pointer, affine flag for tile index t
__device__ __forceinline__ void tile_src(int t, int merged, const float* hin, const float* Wl,
                                         int use_x, const float*& A, const float*& W, int& aff) {
    if (!merged) {
        int pn = t >> 2;
        if (pn & 1) { A = d_neigh + (size_t)(pn >> 1) * NN * DD; aff = 0; }
        else        { A = hin; aff = !use_x; }
        W = Wl + (size_t)pn * 16384;
    } else {
        int p = t >> 2;
        if (p == 0) { A = hin; aff = !use_x; W = Wl; }
        else        { A = d_neigh + (size_t)(p - 1) * NN * DD; aff = 0;
                      W = Wl + (size_t)((p - 1) * 2 + 1) * 16384; }
    }
}

__global__ void __launch_bounds__(256)
gemm_merged_kernel(const float* __restrict__ x, int use_x, int layer,
                   const float* __restrict__ bias, int do_relu, int merged,
                   const float* __restrict__ gprev, const float* __restrict__ bprev) {
    extern __shared__ float sm[];
    float* Abuf[2] = { sm, sm + ATILE };
    float* Bbuf[2] = { sm + 2 * ATILE, sm + 3 * ATILE };
    float* scale_s = sm + 4 * ATILE;
    float* shift_s = scale_s + DD;
    uint32_t smb = (uint32_t)__cvta_generic_to_shared(sm);
    uint32_t asu[2] = { smb, smb + ATILE * 4 };
    uint32_t bsu[2] = { smb + 2 * ATILE * 4, smb + 3 * ATILE * 4 };

    const float* hin = use_x ? x : ((layer & 1) ? d_accA : d_accB);
    float* accw = (layer & 1) ? d_accB : d_accA;
    const float* Wl = d_Wt + (size_t)layer * NET * 2 * DD * DD;
    float* stats = d_stats3 + layer * 2 * DD;
    const int n_tiles = merged ? 16 : 24;

    int tid = threadIdx.x, lane = tid & 31, wid = tid >> 5;
    int wm = wid & 3, wn = wid >> 2;
    int m0 = blockIdx.x * 128;

    if (!use_x && tid < DD) {
        const float* st = d_stats3 + (layer - 1) * 2 * DD;
        float mu = st[tid] * (1.0f / NN);
        float var = st[DD + tid] * (1.0f / NN) - mu * mu;
        float sc = __ldg(gprev + tid) * rsqrtf(var + EPS);
        scale_s[tid] = sc;
        shift_s[tid] = __ldg(bprev + tid) - mu * sc;
    }
    __syncthreads();

    uint32_t aoffb[2];
#pragma unroll
    for (int mf = 0; mf < 2; mf++)
        aoffb[mf] = ((wm * 32 + mf * 16 + (lane & 15)) * ASTRIDE + (lane >> 4) * 4) * 4;
    uint32_t boffb[4];
#pragma unroll
    for (int nf2 = 0; nf2 < 4; nf2++) {
        int n = wn * 64 + nf2 * 16 + (lane & 7) + ((lane >> 4) << 3);
        boffb[nf2] = (n * ASTRIDE + ((lane >> 3) & 1) * 4) * 4;
    }

    float facc[2][8][4], acc[2][8][4];
#pragma unroll
    for (int i = 0; i < 2; i++)
#pragma unroll
        for (int j = 0; j < 8; j++)
#pragma unroll
            for (int e = 0; e < 4; e++) { facc[i][j][e] = 0.f; acc[i][j][e] = 0.f; }

    float4 ra[4], rb[4];
    {
        const float *A, *W; int aff;
        tile_src(0, merged, hin, Wl, use_x, A, W, aff);
        ldgA(ra, A, m0, 0, tid, aff, scale_s, shift_s);
        ldgB(rb, W, 0, tid);
        stsA(Abuf[0], ra, tid);
        stsB(Bbuf[0], rb, tid);
    }
    __syncthreads();

#pragma unroll 1
    for (int t = 0; t < n_tiles; t++) {
        const int cur = t & 1;
        if (t < n_tiles - 1) {
            const float *A, *W; int aff;
            tile_src(t + 1, merged, hin, Wl, use_x, A, W, aff);
            ldgA(ra, A, m0, ((t + 1) & 3) * 32, tid, aff, scale_s, shift_s);
            ldgB(rb, W, ((t + 1) & 3) * 32, tid);
        }
#pragma unroll
        for (int ks = 0; ks < 4; ks++) {
            uint32_t af[2][4];
            ldsm4(af[0], asu[cur] + aoffb[0] + ks * 32);
            ldsm4(af[1], asu[cur] + aoffb[1] + ks * 32);
            uint32_t bf[4][4];
#pragma unroll
            for (int nf2 = 0; nf2 < 4; nf2++)
                ldsm4(bf[nf2], bsu[cur] + boffb[nf2] + ks * 32);
#pragma unroll
            for (int mf = 0; mf < 2; mf++)
#pragma unroll
                for (int nf = 0; nf < 8; nf++) {
                    int q = (nf & 1) * 2;
                    mma8(acc[mf][nf], af[mf], bf[nf >> 1][q], bf[nf >> 1][q + 1]);
                }
        }
        // fold points: non-merged at 7/15/23 (per etype); merged at 15 (all at once)
        bool fold = merged ? (t == 15) : (t == 7 || t == 15 || t == 23);
        if (fold) {
#pragma unroll
            for (int nf = 0; nf < 8; nf++) {
                int n = wn * 64 + nf * 8 + ((lane & 3) << 1);
                float b0, b1;
                if (merged) {
                    b0 = __ldg(bias + n) + __ldg(bias + DD + n) + __ldg(bias + 2 * DD + n);
                    b1 = __ldg(bias + n + 1) + __ldg(bias + DD + n + 1) + __ldg(bias + 2 * DD + n + 1);
                } else {
                    const float* be = bias + (t >> 3) * DD;
                    b0 = __ldg(be + n); b1 = __ldg(be + n + 1);
                }
#pragma unroll
                for (int mf = 0; mf < 2; mf++) {
                    float v0 = acc[mf][nf][0] + b0, v1 = acc[mf][nf][1] + b1;
                    float v2 = acc[mf][nf][2] + b0, v3 = acc[mf][nf][3] + b1;
                    if (do_relu) {
                        v0 = fmaxf(v0, 0.f); v1 = fmaxf(v1, 0.f);
                        v2 = fmaxf(v2, 0.f); v3 = fmaxf(v3, 0.f);
                    }
                    facc[mf][nf][0] += v0; facc[mf][nf][1] += v1;
                    facc[mf][nf][2] += v2; facc[mf][nf][3] += v3;
                    acc[mf][nf][0] = 0.f; acc[mf][nf][1] = 0.f;
                    acc[mf][nf][2] = 0.f; acc[mf][nf][3] = 0.f;
                }
            }
        }
        if (t < n_tiles - 1) {
            __syncthreads();
            stsA(Abuf[1 - cur], ra, tid);
            stsB(Bbuf[1 - cur], rb, tid);
            __syncthreads();
        }
    }

    int r0 = m0 + wm * 32 + (lane >> 2);
    int rr[2] = { r0, r0 + 16 };
#pragma unroll
    for (int nf = 0; nf < 8; nf++) {
        int n = wn * 64 + nf * 8 + ((lane & 3) << 1);
        float s0 = 0.f, s1 = 0.f, q0 = 0.f, q1 = 0.f;
#pragma unroll
        for (int mf = 0; mf < 2; mf++) {
            int r = rr[mf];
            float v0 = facc[mf][nf][0], v1 = facc[mf][nf][1];
            float v2 = facc[mf][nf][2], v3 = facc[mf][nf][3];
            if (r < NN) {
                *reinterpret_cast<float2*>(accw + (size_t)r * DD + n) = make_float2(v0, v1);
                s0 += v0; s1 += v1;
                q0 = fmaf(v0, v0, q0); q1 = fmaf(v1, v1, q1);
            }
            if (r + 8 < NN) {
                *reinterpret_cast<float2*>(accw + (size_t)(r + 8) * DD + n) = make_float2(v2, v3);
                s0 += v2; s1 += v3;
                q0 = fmaf(v2, v2, q0); q1 = fmaf(v3, v3, q1);
            }
        }
#pragma unroll
        for (int o = 4; o < 32; o <<= 1) {
            s0 += __shfl_xor_sync(0xFFFFFFFFu, s0, o);
            s1 += __shfl_xor_sync(0xFFFFFFFFu, s1, o);
            q0 += __shfl_xor_sync(0xFFFFFFFFu, q0, o);
            q1 += __shfl_xor_sync(0xFFFFFFFFu, q1, o);
        }
        if (lane < 4) {
            atomicAdd(stats + n, s0);
            atomicAdd(stats + n + 1, s1);
            atomicAdd(stats + DD + n, q0);
            atomicAdd(stats + DD + n + 1, q1);
        }
    }
}

// ======================= final BatchNorm (layer 2 -> out) =======================

__global__ void bn_final_kernel(const float* __restrict__ gamma,
                                const float* __restrict__ beta,
                                float* __restrict__ outp) {
    __shared__ float scale_s[DD];
    __shared__ float shift_s[DD];
    if (threadIdx.x < DD) {
        int c = threadIdx.x;
        const float* st = d_stats3 + 2 * 2 * DD;
        float mu = st[c] * (1.0f / NN);
        float var = st[DD + c] * (1.0f / NN) - mu * mu;
        float sc = __ldg(gamma + c) * rsqrtf(var + EPS);
        scale_s[c] = sc;
        shift_s[c] = __ldg(beta + c) - mu * sc;
    }
    __syncthreads();
    size_t i = (size_t)blockIdx.x * blockDim.x + threadIdx.x;
    if (i >= (size_t)NN * DD / 4) return;
    int col = (int)((i * 4) & (DD - 1));
    float4 v = reinterpret_cast<const float4*>(d_accA)[i];   // layer 2 writes accA
    float4 o;
    o.x = v.x * scale_s[col + 0] + shift_s[col + 0];
    o.y = v.y * scale_s[col + 1] + shift_s[col + 1];
    o.z = v.z * scale_s[col + 2] + shift_s[col + 2];
    o.w = v.w * scale_s[col + 3] + shift_s[col + 3];
    reinterpret_cast<float4*>(outp)[i] = o;
}

// ======================= launch =======================

extern "C" void kernel_launch(void* const* d_in, const int* in_sizes, int n_in,
                              void* d_out, int out_size) {
    const float* x     = (const float*)d_in[0];
    const int*   src   = (const int*)d_in[1];
    const int*   dst   = (const int*)d_in[2];
    const float* Ws    = (const float*)d_in[3];
    const float* Wn    = (const float*)d_in[4];
    const float* bias  = (const float*)d_in[5];
    const float* gamma = (const float*)d_in[6];
    const float* beta  = (const float*)d_in[7];
    float* out = (float*)d_out;

    cudaFuncSetAttribute(gemm_merged_kernel,
                         cudaFuncAttributeMaxDynamicSharedMemorySize, SMEM_BYTES);

    {
        int n = NL * NET * 2 * DD * DD;
        wt_prep_kernel<<<(n + 255) / 256, 256>>>(Ws, Wn);
    }
    {
        zero_cnt_kernel<<<(NROWS + 255) / 256, 256>>>();
        int ne = NET * NE;
        deg_count_kernel<<<(ne + 255) / 256, 256>>>(dst);
        scan1_kernel<<<SCAN_BLK, 256>>>();
        scan2_kernel<<<1, 512>>>();
        scan3_kernel<<<SCAN_BLK, 256>>>();
        permute_kernel<<<(ne + 255) / 256, 256>>>(src, dst);
    }

    const int gemm_blocks = (NN + 127) / 128;
    const int gather_blocks = (NROWS * 32 + 255) / 256;
    const int bn4_blocks = (NN * DD / 4 + 255) / 256;

    for (int l = 0; l < NL; l++) {
        int pl = (l > 0) ? (l - 1) : 0;
        gather_kernel<<<gather_blocks, 256>>>(x, (l == 0), l,
                                              gamma + (size_t)pl * DD, beta + (size_t)pl * DD);
        gemm_merged_kernel<<<gemm_blocks, 256, SMEM_BYTES>>>(
            x, (l == 0), l, bias + (size_t)l * NET * DD, (l < NL - 1), (l == 2),
            gamma + (size_t)pl * DD, beta + (size_t)pl * DD);
    }
    bn_final_kernel<<<bn4_blocks, 256>>>(gamma + 2 * DD, beta + 2 * DD, out);
}

// round 10
// speedup vs baseline: 1.4370x; 1.4172x over previous
#include <cuda_runtime.h>
#include <cstdint>

#define NN 100000
#define NE 600000
#define NET 3
#define NL 3
#define DD 128
#define EPS 1e-5f
#define NROWS (NET * NN)
#define SCAN_BLK 293

// ---------------- static device scratch (device-code access ONLY) ----------------
__device__ float d_accA[(size_t)NN * DD];
__device__ float d_accB[(size_t)NN * DD];
__device__ float d_neigh[(size_t)NET * NN * DD];
__device__ float d_invdeg[NROWS];
__device__ float d_stats3[NL * 2 * DD];
__device__ float d_Wt[(size_t)NL * NET * 2 * DD * DD];  // W^T tf32: [l][e][sel][n][kk]
__device__ int   d_cnt[NROWS];
__device__ int   d_rowoff[NROWS + 1];
__device__ int   d_bsums[512];
__device__ int   d_esrc[NET * NE];

// ======================= prep: CSR build =======================

__global__ void zero_cnt_kernel() {
    int i = blockIdx.x * blockDim.x + threadIdx.x;
    if (i < NROWS) d_cnt[i] = 0;
    if (i < NL * 2 * DD) d_stats3[i] = 0.f;
}
__global__ void deg_count_kernel(const int* __restrict__ dst) {
    int idx = blockIdx.x * blockDim.x + threadIdx.x;
    if (idx >= NET * NE) return;
    int k = idx / NE;
    atomicAdd(&d_cnt[k * NN + __ldg(dst + idx)], 1);
}
__global__ void scan1_kernel() {
    int base = blockIdx.x * 1024;
    int t = threadIdx.x;
    int sum = 0;
#pragma unroll
    for (int j = 0; j < 4; j++) {
        int i = base + t * 4 + j;
        if (i < NROWS) sum += d_cnt[i];
    }
#pragma unroll
    for (int o = 16; o; o >>= 1) sum += __shfl_down_sync(0xFFFFFFFFu, sum, o);
    __shared__ int ws[8];
    if ((t & 31) == 0) ws[t >> 5] = sum;
    __syncthreads();
    if (t == 0) {
        int v = 0;
#pragma unroll
        for (int i = 0; i < 8; i++) v += ws[i];
        d_bsums[blockIdx.x] = v;
    }
}
__global__ void scan2_kernel() {
    __shared__ int s[512];
    int t = threadIdx.x;
    int orig = (t < SCAN_BLK) ? d_bsums[t] : 0;
    s[t] = orig;
    __syncthreads();
#pragma unroll
    for (int o = 1; o < 512; o <<= 1) {
        int v = (t >= o) ? s[t - o] : 0;
        __syncthreads();
        s[t] += v;
        __syncthreads();
    }
    if (t < SCAN_BLK) d_bsums[t] = s[t] - orig;
}
__global__ void scan3_kernel() {
    int base = blockIdx.x * 1024;
    int t = threadIdx.x, lane = t & 31, warp = t >> 5;
    int vals[4];
    int tsum = 0;
#pragma unroll
    for (int j = 0; j < 4; j++) {
        int i = base + t * 4 + j;
        vals[j] = (i < NROWS) ? d_cnt[i] : 0;
        tsum += vals[j];
    }
    int inc = tsum;
#pragma unroll
    for (int o = 1; o < 32; o <<= 1) {
        int v = __shfl_up_sync(0xFFFFFFFFu, inc, o);
        if (lane >= o) inc += v;
    }
    int texcl = inc - tsum;
    __shared__ int wsum[8];
    if (lane == 31) wsum[warp] = inc;
    __syncthreads();
    __shared__ int woff[8];
    if (t == 0) {
        int a = 0;
#pragma unroll
        for (int i = 0; i < 8; i++) { woff[i] = a; a += wsum[i]; }
    }
    __syncthreads();
    int run = d_bsums[blockIdx.x] + woff[warp] + texcl;
#pragma unroll
    for (int j = 0; j < 4; j++) {
        int i = base + t * 4 + j;
        if (i < NROWS) {
            d_rowoff[i] = run;
            d_invdeg[i] = 1.0f / fmaxf((float)vals[j], 1.0f);
            d_cnt[i] = 0;
            run += vals[j];
        }
    }
    if (blockIdx.x == 0 && t == 0) d_rowoff[NROWS] = NET * NE;
}
__global__ void permute_kernel(const int* __restrict__ src, const int* __restrict__ dst) {
    int idx = blockIdx.x * blockDim.x + threadIdx.x;
    if (idx >= NET * NE) return;
    int k = idx / NE;
    int g = k * NN + __ldg(dst + idx);
    int pos = d_rowoff[g] + atomicAdd(&d_cnt[g], 1);
    d_esrc[pos] = __ldg(src + idx);
}

__device__ __forceinline__ uint32_t f2tf32(float x) {
    uint32_t r;
    asm("cvt.rna.tf32.f32 %0, %1;" : "=r"(r) : "f"(x));
    return r;
}

// W^T + tf32; layer-2 slot (e=0,self) holds merged sum_e(Ws_e)
__global__ void wt_prep_kernel(const float* __restrict__ Ws, const float* __restrict__ Wn) {
    int i = blockIdx.x * blockDim.x + threadIdx.x;
    if (i >= NL * NET * 2 * DD * DD) return;
    int kk = i & 127;
    int n = (i >> 7) & 127;
    int sel = (i >> 14) & 1;
    int m = i >> 15;
    float v;
    if (m == 2 * NET && sel == 0) {
        v = __ldg(Ws + (size_t)6 * 16384 + kk * DD + n)
          + __ldg(Ws + (size_t)7 * 16384 + kk * DD + n)
          + __ldg(Ws + (size_t)8 * 16384 + kk * DD + n);
    } else {
        v = __ldg((sel ? Wn : Ws) + (size_t)m * 16384 + kk * DD + n);
    }
    d_Wt[i] = __uint_as_float(f2tf32(v));
}

// ======================= gather (CSR mean, BN-of-prev folded in) =======================
__global__ void gather_kernel(const float* __restrict__ x, int use_x, int layer,
                              const float* __restrict__ gprev, const float* __restrict__ bprev) {
    const float* hin = use_x ? x : ((layer & 1) ? d_accA : d_accB);
    int w = (blockIdx.x * blockDim.x + threadIdx.x) >> 5;
    int lane = threadIdx.x & 31;
    if (w >= NROWS) return;

    float4 sc4 = make_float4(1.f, 1.f, 1.f, 1.f);
    float4 sh4 = make_float4(0.f, 0.f, 0.f, 0.f);
    if (!use_x) {
        const float* st = d_stats3 + (layer - 1) * 2 * DD;
        float4 s = __ldg(reinterpret_cast<const float4*>(st) + lane);
        float4 q = __ldg(reinterpret_cast<const float4*>(st + DD) + lane);
        float4 gm = __ldg(reinterpret_cast<const float4*>(gprev) + lane);
        float4 bt = __ldg(reinterpret_cast<const float4*>(bprev) + lane);
        float mu0 = s.x / NN, mu1 = s.y / NN, mu2 = s.z / NN, mu3 = s.w / NN;
        sc4.x = gm.x * rsqrtf(q.x / NN - mu0 * mu0 + EPS);
        sc4.y = gm.y * rsqrtf(q.y / NN - mu1 * mu1 + EPS);
        sc4.z = gm.z * rsqrtf(q.z / NN - mu2 * mu2 + EPS);
        sc4.w = gm.w * rsqrtf(q.w / NN - mu3 * mu3 + EPS);
        sh4.x = bt.x - mu0 * sc4.x; sh4.y = bt.y - mu1 * sc4.y;
        sh4.z = bt.z - mu2 * sc4.z; sh4.w = bt.w - mu3 * sc4.w;
    }

    int o0 = __ldg(&d_rowoff[w]);
    int o1 = __ldg(&d_rowoff[w + 1]);
    float4 a = make_float4(0.f, 0.f, 0.f, 0.f);
    if (o1 > o0) {
        int s = __ldg(&d_esrc[o0]);
        for (int e = o0; e < o1; e++) {
            int sn = (e + 1 < o1) ? __ldg(&d_esrc[e + 1]) : 0;
            float4 v = __ldg(reinterpret_cast<const float4*>(hin + (size_t)s * DD) + lane);
            a.x += v.x; a.y += v.y; a.z += v.z; a.w += v.w;
            s = sn;
        }
        float iv = d_invdeg[w];
        a.x *= iv; a.y *= iv; a.z *= iv; a.w *= iv;
        a.x = fmaf(a.x, sc4.x, sh4.x); a.y = fmaf(a.y, sc4.y, sh4.y);
        a.z = fmaf(a.z, sc4.z, sh4.z); a.w = fmaf(a.w, sc4.w, sh4.w);
    }
    reinterpret_cast<float4*>(d_neigh)[(size_t)w * 32 + lane] = a;
}

// ======================= templated tf32 mma GEMM (FULLY UNROLLED schedule) =======================

#define ASTRIDE 36
#define ATILE (128 * ASTRIDE)
#define SMEM_BYTES ((4 * ATILE + 2 * DD) * 4)

__device__ __forceinline__ void ldsm4(uint32_t* r, uint32_t addr) {
    asm volatile("ldmatrix.sync.aligned.m8n8.x4.shared.b16 {%0,%1,%2,%3}, [%4];"
                 : "=r"(r[0]), "=r"(r[1]), "=r"(r[2]), "=r"(r[3]) : "r"(addr));
}
__device__ __forceinline__ void mma8(float* c, const uint32_t* a, uint32_t b0, uint32_t b1) {
    asm volatile("mma.sync.aligned.m16n8k8.row.col.f32.tf32.tf32.f32 "
                 "{%0,%1,%2,%3}, {%4,%5,%6,%7}, {%8,%9}, {%0,%1,%2,%3};"
                 : "+f"(c[0]), "+f"(c[1]), "+f"(c[2]), "+f"(c[3])
                 : "r"(a[0]), "r"(a[1]), "r"(a[2]), "r"(a[3]), "r"(b0), "r"(b1));
}

__device__ __forceinline__ void ldgA(float4* ra, const float* __restrict__ src,
                                     int m0, int koff, int tid, int affine,
                                     const float* __restrict__ scale_s,
                                     const float* __restrict__ shift_s) {
#pragma unroll
    for (int t = 0; t < 4; t++) {
        int c = tid + t * 256;
        int gr = m0 + (c >> 3);
        float4 v = make_float4(0.f, 0.f, 0.f, 0.f);
        if (gr < NN) {
            v = __ldg(reinterpret_cast<const float4*>(src + (size_t)gr * DD + koff) + (c & 7));
            if (affine) {
                int col = koff + (c & 7) * 4;
                float4 sc = *reinterpret_cast<const float4*>(scale_s + col);
                float4 sh = *reinterpret_cast<const float4*>(shift_s + col);
                v.x = fmaf(v.x, sc.x, sh.x); v.y = fmaf(v.y, sc.y, sh.y);
                v.z = fmaf(v.z, sc.z, sh.z); v.w = fmaf(v.w, sc.w, sh.w);
            }
        }
        ra[t] = v;
    }
}
__device__ __forceinline__ void ldgB(float4* rb, const float* __restrict__ W,
                                     int koff, int tid) {
#pragma unroll
    for (int t = 0; t < 4; t++) {
        int c = tid + t * 256;
        rb[t] = __ldg(reinterpret_cast<const float4*>(W + (size_t)(c >> 3) * DD + koff) + (c & 7));
    }
}
__device__ __forceinline__ void stsA(float* As, const float4* ra, int tid) {
#pragma unroll
    for (int t = 0; t < 4; t++) {
        int c = tid + t * 256;
        uint4 u;
        u.x = f2tf32(ra[t].x); u.y = f2tf32(ra[t].y);
        u.z = f2tf32(ra[t].z); u.w = f2tf32(ra[t].w);
        *reinterpret_cast<uint4*>(As + (c >> 3) * ASTRIDE + (c & 7) * 4) = u;
    }
}
__device__ __forceinline__ void stsB(float* Bs, const float4* rb, int tid) {
#pragma unroll
    for (int t = 0; t < 4; t++) {
        int c = tid + t * 256;
        *reinterpret_cast<float4*>(Bs + (c >> 3) * ASTRIDE + (c & 7) * 4) = rb[t];
    }
}

template<bool MERGED>
__global__ void __launch_bounds__(256)
gemm_tpl_kernel(const float* __restrict__ x, int use_x, int layer,
                const float* __restrict__ bias, int do_relu,
                const float* __restrict__ gprev, const float* __restrict__ bprev) {
    extern __shared__ float sm[];
    float* Abuf[2] = { sm, sm + ATILE };
    float* Bbuf[2] = { sm + 2 * ATILE, sm + 3 * ATILE };
    float* scale_s = sm + 4 * ATILE;
    float* shift_s = scale_s + DD;
    uint32_t smb = (uint32_t)__cvta_generic_to_shared(sm);
    uint32_t asu[2] = { smb, smb + ATILE * 4 };
    uint32_t bsu[2] = { smb + 2 * ATILE * 4, smb + 3 * ATILE * 4 };

    const float* hin = use_x ? x : ((layer & 1) ? d_accA : d_accB);
    float* accw = (layer & 1) ? d_accB : d_accA;
    const float* Wl = d_Wt + (size_t)layer * NET * 2 * DD * DD;
    float* stats = d_stats3 + layer * 2 * DD;
    constexpr int NT = MERGED ? 16 : 24;

    int tid = threadIdx.x, lane = tid & 31, wid = tid >> 5;
    int wm = wid & 3, wn = wid >> 2;
    int m0 = blockIdx.x * 128;

    if (!use_x && tid < DD) {
        const float* st = d_stats3 + (layer - 1) * 2 * DD;
        float mu = st[tid] * (1.0f / NN);
        float var = st[DD + tid] * (1.0f / NN) - mu * mu;
        float sc = __ldg(gprev + tid) * rsqrtf(var + EPS);
        scale_s[tid] = sc;
        shift_s[tid] = __ldg(bprev + tid) - mu * sc;
    }
    __syncthreads();

    uint32_t aoffb[2];
#pragma unroll
    for (int mf = 0; mf < 2; mf++)
        aoffb[mf] = ((wm * 32 + mf * 16 + (lane & 15)) * ASTRIDE + (lane >> 4) * 4) * 4;
    uint32_t boffb[4];
#pragma unroll
    for (int nf2 = 0; nf2 < 4; nf2++) {
        int n = wn * 64 + nf2 * 16 + (lane & 7) + ((lane >> 4) << 3);
        boffb[nf2] = (n * ASTRIDE + ((lane >> 3) & 1) * 4) * 4;
    }

    float facc[2][8][4], acc[2][8][4];
#pragma unroll
    for (int i = 0; i < 2; i++)
#pragma unroll
        for (int j = 0; j < 8; j++)
#pragma unroll
            for (int e = 0; e < 4; e++) { facc[i][j][e] = 0.f; acc[i][j][e] = 0.f; }

    float4 ra[4], rb[4];
    ldgA(ra, hin, m0, 0, tid, !use_x, scale_s, shift_s);
    ldgB(rb, Wl, 0, tid);
    stsA(Abuf[0], ra, tid);
    stsB(Bbuf[0], rb, tid);
    __syncthreads();

#pragma unroll
    for (int t = 0; t < NT; t++) {
        const int cur = t & 1;
        if (t < NT - 1) {
            const int tn = t + 1;
            // compile-time resolved under full unroll:
            const float* A;
            const float* W;
            int aff;
            if (!MERGED) {
                const int pn = tn >> 2;
                if (pn & 1) { A = d_neigh + (size_t)(pn >> 1) * NN * DD; aff = 0; }
                else        { A = hin; aff = !use_x; }
                W = Wl + (size_t)pn * 16384;
            } else {
                const int p = tn >> 2;
                if (p == 0) { A = hin; aff = 1; W = Wl; }
                else        { A = d_neigh + (size_t)(p - 1) * NN * DD; aff = 0;
                              W = Wl + (size_t)((p - 1) * 2 + 1) * 16384; }
            }
            ldgA(ra, A, m0, (tn & 3) * 32, tid, aff, scale_s, shift_s);
            ldgB(rb, W, (tn & 3) * 32, tid);
        }
#pragma unroll
        for (int ks = 0; ks < 4; ks++) {
            uint32_t af[2][4];
            ldsm4(af[0], asu[cur] + aoffb[0] + ks * 32);
            ldsm4(af[1], asu[cur] + aoffb[1] + ks * 32);
            uint32_t bf[4][4];
#pragma unroll
            for (int nf2 = 0; nf2 < 4; nf2++)
                ldsm4(bf[nf2], bsu[cur] + boffb[nf2] + ks * 32);
#pragma unroll
            for (int mf = 0; mf < 2; mf++)
#pragma unroll
                for (int nf = 0; nf < 8; nf++) {
                    int q = (nf & 1) * 2;
                    mma8(acc[mf][nf], af[mf], bf[nf >> 1][q], bf[nf >> 1][q + 1]);
                }
        }
        const bool fold = MERGED ? (t == NT - 1) : ((t & 7) == 7);
        if (fold) {
#pragma unroll
            for (int nf = 0; nf < 8; nf++) {
                int n = wn * 64 + nf * 8 + ((lane & 3) << 1);
                float b0, b1;
                if (MERGED) {
                    b0 = __ldg(bias + n) + __ldg(bias + DD + n) + __ldg(bias + 2 * DD + n);
                    b1 = __ldg(bias + n + 1) + __ldg(bias + DD + n + 1) + __ldg(bias + 2 * DD + n + 1);
                } else {
                    const float* be = bias + (t >> 3) * DD;
                    b0 = __ldg(be + n); b1 = __ldg(be + n + 1);
                }
#pragma unroll
                for (int mf = 0; mf < 2; mf++) {
                    float v0 = acc[mf][nf][0] + b0, v1 = acc[mf][nf][1] + b1;
                    float v2 = acc[mf][nf][2] + b0, v3 = acc[mf][nf][3] + b1;
                    if (do_relu) {
                        v0 = fmaxf(v0, 0.f); v1 = fmaxf(v1, 0.f);
                        v2 = fmaxf(v2, 0.f); v3 = fmaxf(v3, 0.f);
                    }
                    facc[mf][nf][0] += v0; facc[mf][nf][1] += v1;
                    facc[mf][nf][2] += v2; facc[mf][nf][3] += v3;
                    acc[mf][nf][0] = 0.f; acc[mf][nf][1] = 0.f;
                    acc[mf][nf][2] = 0.f; acc[mf][nf][3] = 0.f;
                }
            }
        }
        if (t < NT - 1) {
            __syncthreads();
            stsA(Abuf[1 - cur], ra, tid);
            stsB(Bbuf[1 - cur], rb, tid);
            __syncthreads();
        }
    }

    int r0 = m0 + wm * 32 + (lane >> 2);
    int rr[2] = { r0, r0 + 16 };
#pragma unroll
    for (int nf = 0; nf < 8; nf++) {
        int n = wn * 64 + nf * 8 + ((lane & 3) << 1);
        float s0 = 0.f, s1 = 0.f, q0 = 0.f, q1 = 0.f;
#pragma unroll
        for (int mf = 0; mf < 2; mf++) {
            int r = rr[mf];
            float v0 = facc[mf][nf][0], v1 = facc[mf][nf][1];
            float v2 = facc[mf][nf][2], v3 = facc[mf][nf][3];
            if (r < NN) {
                *reinterpret_cast<float2*>(accw + (size_t)r * DD + n) = make_float2(v0, v1);
                s0 += v0; s1 += v1;
                q0 = fmaf(v0, v0, q0); q1 = fmaf(v1, v1, q1);
            }
            if (r + 8 < NN) {
                *reinterpret_cast<float2*>(accw + (size_t)(r + 8) * DD + n) = make_float2(v2, v3);
                s0 += v2; s1 += v3;
                q0 = fmaf(v2, v2, q0); q1 = fmaf(v3, v3, q1);
            }
        }
#pragma unroll
        for (int o = 4; o < 32; o <<= 1) {
            s0 += __shfl_xor_sync(0xFFFFFFFFu, s0, o);
            s1 += __shfl_xor_sync(0xFFFFFFFFu, s1, o);
            q0 += __shfl_xor_sync(0xFFFFFFFFu, q0, o);
            q1 += __shfl_xor_sync(0xFFFFFFFFu, q1, o);
        }
        if (lane < 4) {
            atomicAdd(stats + n, s0);
            atomicAdd(stats + n + 1, s1);
            atomicAdd(stats + DD + n, q0);
            atomicAdd(stats + DD + n + 1, q1);
        }
    }
}

// ======================= final BatchNorm (layer 2 -> out) =======================

__global__ void bn_final_kernel(const float* __restrict__ gamma,
                                const float* __restrict__ beta,
                                float* __restrict__ outp) {
    __shared__ float scale_s[DD];
    __shared__ float shift_s[DD];
    if (threadIdx.x < DD) {
        int c = threadIdx.x;
        const float* st = d_stats3 + 2 * 2 * DD;
        float mu = st[c] * (1.0f / NN);
        float var = st[DD + c] * (1.0f / NN) - mu * mu;
        float sc = __ldg(gamma + c) * rsqrtf(var + EPS);
        scale_s[c] = sc;
        shift_s[c] = __ldg(beta + c) - mu * sc;
    }
    __syncthreads();
    size_t i = (size_t)blockIdx.x * blockDim.x + threadIdx.x;
    if (i >= (size_t)NN * DD / 4) return;
    int col = (int)((i * 4) & (DD - 1));
    float4 v = reinterpret_cast<const float4*>(d_accA)[i];   // layer 2 writes accA
    float4 o;
    o.x = v.x * scale_s[col + 0] + shift_s[col + 0];
    o.y = v.y * scale_s[col + 1] + shift_s[col + 1];
    o.z = v.z * scale_s[col + 2] + shift_s[col + 2];
    o.w = v.w * scale_s[col + 3] + shift_s[col + 3];
    reinterpret_cast<float4*>(outp)[i] = o;
}

// ======================= launch =======================

extern "C" void kernel_launch(void* const* d_in, const int* in_sizes, int n_in,
                              void* d_out, int out_size) {
    const float* x     = (const float*)d_in[0];
    const int*   src   = (const int*)d_in[1];
    const int*   dst   = (const int*)d_in[2];
    const float* Ws    = (const float*)d_in[3];
    const float* Wn    = (const float*)d_in[4];
    const float* bias  = (const float*)d_in[5];
    const float* gamma = (const float*)d_in[6];
    const float* beta  = (const float*)d_in[7];
    float* out = (float*)d_out;

    cudaFuncSetAttribute(gemm_tpl_kernel<false>,
                         cudaFuncAttributeMaxDynamicSharedMemorySize, SMEM_BYTES);
    cudaFuncSetAttribute(gemm_tpl_kernel<true>,
                         cudaFuncAttributeMaxDynamicSharedMemorySize, SMEM_BYTES);

    {
        int n = NL * NET * 2 * DD * DD;
        wt_prep_kernel<<<(n + 255) / 256, 256>>>(Ws, Wn);
    }
    {
        zero_cnt_kernel<<<(NROWS + 255) / 256, 256>>>();
        int ne = NET * NE;
        deg_count_kernel<<<(ne + 255) / 256, 256>>>(dst);
        scan1_kernel<<<SCAN_BLK, 256>>>();
        scan2_kernel<<<1, 512>>>();
        scan3_kernel<<<SCAN_BLK, 256>>>();
        permute_kernel<<<(ne + 255) / 256, 256>>>(src, dst);
    }

    const int gemm_blocks = (NN + 127) / 128;
    const int gather_blocks = (NROWS * 32 + 255) / 256;
    const int bn4_blocks = (NN * DD / 4 + 255) / 256;

    for (int l = 0; l < NL; l++) {
        int pl = (l > 0) ? (l - 1) : 0;
        gather_kernel<<<gather_blocks, 256>>>(x, (l == 0), l,
                                              gamma + (size_t)pl * DD, beta + (size_t)pl * DD);
        if (l == 2)
            gemm_tpl_kernel<true><<<gemm_blocks, 256, SMEM_BYTES>>>(
                x, 0, l, bias + (size_t)l * NET * DD, 0,
                gamma + (size_t)pl * DD, beta + (size_t)pl * DD);
        else
            gemm_tpl_kernel<false><<<gemm_blocks, 256, SMEM_BYTES>>>(
                x, (l == 0), l, bias + (size_t)l * NET * DD, 1,
                gamma + (size_t)pl * DD, beta + (size_t)pl * DD);
    }
    bn_final_kernel<<<bn4_blocks, 256>>>(gamma + 2 * DD, beta + 2 * DD, out);
}

// round 11
// speedup vs baseline: 1.6499x; 1.1481x over previous
#include <cuda_runtime.h>
#include <cstdint>

#define NN 100000
#define NE 600000
#define NET 3
#define NL 3
#define DD 128
#define EPS 1e-5f
#define NROWS (NET * NN)
#define SCAN_BLK 293

// ---------------- static device scratch (device-code access ONLY) ----------------
__device__ float d_h[(size_t)NN * DD];
__device__ float d_neigh[(size_t)NET * NN * DD];
__device__ float d_acc[(size_t)NN * DD];
__device__ float d_invdeg[NROWS];
__device__ float d_stats3[NL * 2 * DD];
__device__ float d_Wt[(size_t)NL * NET * 2 * DD * DD];  // W^T tf32: [l][e][sel][n][kk]
__device__ int   d_cnt[NROWS];
__device__ int   d_rowoff[NROWS + 1];
__device__ int   d_bsums[512];
__device__ int   d_esrc[NET * NE];

// ======================= prep: CSR build =======================

__global__ void zero_cnt_kernel() {
    int i = blockIdx.x * blockDim.x + threadIdx.x;
    if (i < NROWS) d_cnt[i] = 0;
    if (i < NL * 2 * DD) d_stats3[i] = 0.f;
}
__global__ void deg_count_kernel(const int* __restrict__ dst) {
    int idx = blockIdx.x * blockDim.x + threadIdx.x;
    if (idx >= NET * NE) return;
    int k = idx / NE;
    atomicAdd(&d_cnt[k * NN + __ldg(dst + idx)], 1);
}
__global__ void scan1_kernel() {
    int base = blockIdx.x * 1024;
    int t = threadIdx.x;
    int sum = 0;
#pragma unroll
    for (int j = 0; j < 4; j++) {
        int i = base + t * 4 + j;
        if (i < NROWS) sum += d_cnt[i];
    }
#pragma unroll
    for (int o = 16; o; o >>= 1) sum += __shfl_down_sync(0xFFFFFFFFu, sum, o);
    __shared__ int ws[8];
    if ((t & 31) == 0) ws[t >> 5] = sum;
    __syncthreads();
    if (t == 0) {
        int v = 0;
#pragma unroll
        for (int i = 0; i < 8; i++) v += ws[i];
        d_bsums[blockIdx.x] = v;
    }
}
__global__ void scan2_kernel() {
    __shared__ int s[512];
    int t = threadIdx.x;
    int orig = (t < SCAN_BLK) ? d_bsums[t] : 0;
    s[t] = orig;
    __syncthreads();
#pragma unroll
    for (int o = 1; o < 512; o <<= 1) {
        int v = (t >= o) ? s[t - o] : 0;
        __syncthreads();
        s[t] += v;
        __syncthreads();
    }
    if (t < SCAN_BLK) d_bsums[t] = s[t] - orig;
}
__global__ void scan3_kernel() {
    int base = blockIdx.x * 1024;
    int t = threadIdx.x, lane = t & 31, warp = t >> 5;
    int vals[4];
    int tsum = 0;
#pragma unroll
    for (int j = 0; j < 4; j++) {
        int i = base + t * 4 + j;
        vals[j] = (i < NROWS) ? d_cnt[i] : 0;
        tsum += vals[j];
    }
    int inc = tsum;
#pragma unroll
    for (int o = 1; o < 32; o <<= 1) {
        int v = __shfl_up_sync(0xFFFFFFFFu, inc, o);
        if (lane >= o) inc += v;
    }
    int texcl = inc - tsum;
    __shared__ int wsum[8];
    if (lane == 31) wsum[warp] = inc;
    __syncthreads();
    __shared__ int woff[8];
    if (t == 0) {
        int a = 0;
#pragma unroll
        for (int i = 0; i < 8; i++) { woff[i] = a; a += wsum[i]; }
    }
    __syncthreads();
    int run = d_bsums[blockIdx.x] + woff[warp] + texcl;
#pragma unroll
    for (int j = 0; j < 4; j++) {
        int i = base + t * 4 + j;
        if (i < NROWS) {
            d_rowoff[i] = run;
            d_invdeg[i] = 1.0f / fmaxf((float)vals[j], 1.0f);
            d_cnt[i] = 0;
            run += vals[j];
        }
    }
    if (blockIdx.x == 0 && t == 0) d_rowoff[NROWS] = NET * NE;
}
__global__ void permute_kernel(const int* __restrict__ src, const int* __restrict__ dst) {
    int idx = blockIdx.x * blockDim.x + threadIdx.x;
    if (idx >= NET * NE) return;
    int k = idx / NE;
    int g = k * NN + __ldg(dst + idx);
    int pos = d_rowoff[g] + atomicAdd(&d_cnt[g], 1);
    d_esrc[pos] = __ldg(src + idx);
}

__device__ __forceinline__ uint32_t f2tf32(float x) {
    uint32_t r;
    asm("cvt.rna.tf32.f32 %0, %1;" : "=r"(r) : "f"(x));
    return r;
}

// transpose + tf32 round: d_Wt[(m*2+sel)*16384 + n*128 + kk] = tf32(W[m][sel][kk][n])
__global__ void wt_prep_kernel(const float* __restrict__ Ws, const float* __restrict__ Wn) {
    int i = blockIdx.x * blockDim.x + threadIdx.x;
    if (i >= NL * NET * 2 * DD * DD) return;
    int kk = i & 127;
    int n = (i >> 7) & 127;
    int sel = (i >> 14) & 1;
    int m = i >> 15;
    float v = __ldg((sel ? Wn : Ws) + (size_t)m * 16384 + kk * DD + n);
    d_Wt[i] = __uint_as_float(f2tf32(v));
}

// ======================= gather (CSR mean, 4-edge MLP batching) =======================
__global__ void gather_kernel(const float* __restrict__ x, int use_x) {
    const float* hin = use_x ? x : d_h;
    int w = (blockIdx.x * blockDim.x + threadIdx.x) >> 5;
    int lane = threadIdx.x & 31;
    if (w >= NROWS) return;
    int o0 = __ldg(&d_rowoff[w]);
    int o1 = __ldg(&d_rowoff[w + 1]);
    float4 a = make_float4(0.f, 0.f, 0.f, 0.f);
    int e = o0;
    // 4-edge batches: 4 independent row loads in flight
    for (; e + 4 <= o1; e += 4) {
        int s0 = __ldg(&d_esrc[e + 0]);
        int s1 = __ldg(&d_esrc[e + 1]);
        int s2 = __ldg(&d_esrc[e + 2]);
        int s3 = __ldg(&d_esrc[e + 3]);
        float4 v0 = __ldg(reinterpret_cast<const float4*>(hin + (size_t)s0 * DD) + lane);
        float4 v1 = __ldg(reinterpret_cast<const float4*>(hin + (size_t)s1 * DD) + lane);
        float4 v2 = __ldg(reinterpret_cast<const float4*>(hin + (size_t)s2 * DD) + lane);
        float4 v3 = __ldg(reinterpret_cast<const float4*>(hin + (size_t)s3 * DD) + lane);
        a.x += (v0.x + v1.x) + (v2.x + v3.x);
        a.y += (v0.y + v1.y) + (v2.y + v3.y);
        a.z += (v0.z + v1.z) + (v2.z + v3.z);
        a.w += (v0.w + v1.w) + (v2.w + v3.w);
    }
    for (; e < o1; e++) {
        int s = __ldg(&d_esrc[e]);
        float4 v = __ldg(reinterpret_cast<const float4*>(hin + (size_t)s * DD) + lane);
        a.x += v.x; a.y += v.y; a.z += v.z; a.w += v.w;
    }
    float sc = d_invdeg[w];
    a.x *= sc; a.y *= sc; a.z *= sc; a.w *= sc;
    reinterpret_cast<float4*>(d_neigh)[(size_t)w * 32 + lane] = a;
}

// ======================= merged tf32 mma GEMM (all 3 etypes, fused BN-reduce) =======================

#define ASTRIDE 36
#define ATILE (128 * ASTRIDE)
#define SMEM_BYTES (4 * ATILE * 4)

__device__ __forceinline__ void ldsm4(uint32_t* r, uint32_t addr) {
    asm volatile("ldmatrix.sync.aligned.m8n8.x4.shared.b16 {%0,%1,%2,%3}, [%4];"
                 : "=r"(r[0]), "=r"(r[1]), "=r"(r[2]), "=r"(r[3]) : "r"(addr));
}
__device__ __forceinline__ void mma8(float* c, const uint32_t* a, uint32_t b0, uint32_t b1) {
    asm volatile("mma.sync.aligned.m16n8k8.row.col.f32.tf32.tf32.f32 "
                 "{%0,%1,%2,%3}, {%4,%5,%6,%7}, {%8,%9}, {%0,%1,%2,%3};"
                 : "+f"(c[0]), "+f"(c[1]), "+f"(c[2]), "+f"(c[3])
                 : "r"(a[0]), "r"(a[1]), "r"(a[2]), "r"(a[3]), "r"(b0), "r"(b1));
}

__device__ __forceinline__ void ldgA(float4* ra, const float* __restrict__ src,
                                     int m0, int koff, int tid) {
#pragma unroll
    for (int t = 0; t < 4; t++) {
        int c = tid + t * 256;
        int gr = m0 + (c >> 3);
        ra[t] = (gr < NN)
            ? __ldg(reinterpret_cast<const float4*>(src + (size_t)gr * DD + koff) + (c & 7))
            : make_float4(0.f, 0.f, 0.f, 0.f);
    }
}
__device__ __forceinline__ void ldgB(float4* rb, const float* __restrict__ W,
                                     int koff, int tid) {
#pragma unroll
    for (int t = 0; t < 4; t++) {
        int c = tid + t * 256;
        rb[t] = __ldg(reinterpret_cast<const float4*>(W + (size_t)(c >> 3) * DD + koff) + (c & 7));
    }
}
__device__ __forceinline__ void stsA(float* As, const float4* ra, int tid) {
#pragma unroll
    for (int t = 0; t < 4; t++) {
        int c = tid + t * 256;
        uint4 u;
        u.x = f2tf32(ra[t].x); u.y = f2tf32(ra[t].y);
        u.z = f2tf32(ra[t].z); u.w = f2tf32(ra[t].w);
        *reinterpret_cast<uint4*>(As + (c >> 3) * ASTRIDE + (c & 7) * 4) = u;
    }
}
__device__ __forceinline__ void stsB(float* Bs, const float4* rb, int tid) {
#pragma unroll
    for (int t = 0; t < 4; t++) {
        int c = tid + t * 256;
        *reinterpret_cast<float4*>(Bs + (c >> 3) * ASTRIDE + (c & 7) * 4) = rb[t];
    }
}

__global__ void __launch_bounds__(256)
gemm_merged_kernel(const float* __restrict__ x, int use_x, int layer,
                   const float* __restrict__ bias, int do_relu) {
    extern __shared__ float sm[];
    float* Abuf[2] = { sm, sm + ATILE };
    float* Bbuf[2] = { sm + 2 * ATILE, sm + 3 * ATILE };
    uint32_t smb = (uint32_t)__cvta_generic_to_shared(sm);
    uint32_t asu[2] = { smb, smb + ATILE * 4 };
    uint32_t bsu[2] = { smb + 2 * ATILE * 4, smb + 3 * ATILE * 4 };

    const float* hin = use_x ? x : d_h;
    const float* Wl = d_Wt + (size_t)layer * NET * 2 * DD * DD;
    float* stats = d_stats3 + layer * 2 * DD;

    int tid = threadIdx.x, lane = tid & 31, wid = tid >> 5;
    int wm = wid & 3, wn = wid >> 2;
    int m0 = blockIdx.x * 128;

    uint32_t aoffb[2];
#pragma unroll
    for (int mf = 0; mf < 2; mf++)
        aoffb[mf] = ((wm * 32 + mf * 16 + (lane & 15)) * ASTRIDE + (lane >> 4) * 4) * 4;
    uint32_t boffb[4];
#pragma unroll
    for (int nf2 = 0; nf2 < 4; nf2++) {
        int n = wn * 64 + nf2 * 16 + (lane & 7) + ((lane >> 4) << 3);
        boffb[nf2] = (n * ASTRIDE + ((lane >> 3) & 1) * 4) * 4;
    }

    float facc[2][8][4], acc[2][8][4];
#pragma unroll
    for (int i = 0; i < 2; i++)
#pragma unroll
        for (int j = 0; j < 8; j++)
#pragma unroll
            for (int e = 0; e < 4; e++) { facc[i][j][e] = 0.f; acc[i][j][e] = 0.f; }

    float4 ra[4], rb[4];
    ldgA(ra, hin, m0, 0, tid);
    ldgB(rb, Wl, 0, tid);
    stsA(Abuf[0], ra, tid);
    stsB(Bbuf[0], rb, tid);
    __syncthreads();

#pragma unroll
    for (int t = 0; t < 24; t++) {
        const int cur = t & 1;
        if (t < 23) {
            const int tn = t + 1, pn = tn >> 2;
            const float* Asrc = (pn & 1) ? (d_neigh + (size_t)(pn >> 1) * NN * DD) : hin;
            ldgA(ra, Asrc, m0, (tn & 3) * 32, tid);
            ldgB(rb, Wl + (size_t)pn * DD * DD, (tn & 3) * 32, tid);
        }
#pragma unroll
        for (int ks = 0; ks < 4; ks++) {
            uint32_t af[2][4];
            ldsm4(af[0], asu[cur] + aoffb[0] + ks * 32);
            ldsm4(af[1], asu[cur] + aoffb[1] + ks * 32);
            uint32_t bf[4][4];
#pragma unroll
            for (int nf2 = 0; nf2 < 4; nf2++)
                ldsm4(bf[nf2], bsu[cur] + boffb[nf2] + ks * 32);
#pragma unroll
            for (int mf = 0; mf < 2; mf++)
#pragma unroll
                for (int nf = 0; nf < 8; nf++) {
                    int q = (nf & 1) * 2;
                    mma8(acc[mf][nf], af[mf], bf[nf >> 1][q], bf[nf >> 1][q + 1]);
                }
        }
        if (t == 7 || t == 15 || t == 23) {
            const float* be = bias + (t >> 3) * DD;
#pragma unroll
            for (int nf = 0; nf < 8; nf++) {
                int n = wn * 64 + nf * 8 + ((lane & 3) << 1);
                float b0 = __ldg(be + n), b1 = __ldg(be + n + 1);
#pragma unroll
                for (int mf = 0; mf < 2; mf++) {
                    float v0 = acc[mf][nf][0] + b0, v1 = acc[mf][nf][1] + b1;
                    float v2 = acc[mf][nf][2] + b0, v3 = acc[mf][nf][3] + b1;
                    if (do_relu) {
                        v0 = fmaxf(v0, 0.f); v1 = fmaxf(v1, 0.f);
                        v2 = fmaxf(v2, 0.f); v3 = fmaxf(v3, 0.f);
                    }
                    facc[mf][nf][0] += v0; facc[mf][nf][1] += v1;
                    facc[mf][nf][2] += v2; facc[mf][nf][3] += v3;
                    acc[mf][nf][0] = 0.f; acc[mf][nf][1] = 0.f;
                    acc[mf][nf][2] = 0.f; acc[mf][nf][3] = 0.f;
                }
            }
        }
        if (t < 23) {
            __syncthreads();
            stsA(Abuf[1 - cur], ra, tid);
            stsB(Bbuf[1 - cur], rb, tid);
            __syncthreads();
        }
    }

    int r0 = m0 + wm * 32 + (lane >> 2);
    int rr[2] = { r0, r0 + 16 };
#pragma unroll
    for (int nf = 0; nf < 8; nf++) {
        int n = wn * 64 + nf * 8 + ((lane & 3) << 1);
        float s0 = 0.f, s1 = 0.f, q0 = 0.f, q1 = 0.f;
#pragma unroll
        for (int mf = 0; mf < 2; mf++) {
            int r = rr[mf];
            float v0 = facc[mf][nf][0], v1 = facc[mf][nf][1];
            float v2 = facc[mf][nf][2], v3 = facc[mf][nf][3];
            if (r < NN) {
                *reinterpret_cast<float2*>(d_acc + (size_t)r * DD + n) = make_float2(v0, v1);
                s0 += v0; s1 += v1;
                q0 = fmaf(v0, v0, q0); q1 = fmaf(v1, v1, q1);
            }
            if (r + 8 < NN) {
                *reinterpret_cast<float2*>(d_acc + (size_t)(r + 8) * DD + n) = make_float2(v2, v3);
                s0 += v2; s1 += v3;
                q0 = fmaf(v2, v2, q0); q1 = fmaf(v3, v3, q1);
            }
        }
#pragma unroll
        for (int o = 4; o < 32; o <<= 1) {
            s0 += __shfl_xor_sync(0xFFFFFFFFu, s0, o);
            s1 += __shfl_xor_sync(0xFFFFFFFFu, s1, o);
            q0 += __shfl_xor_sync(0xFFFFFFFFu, q0, o);
            q1 += __shfl_xor_sync(0xFFFFFFFFu, q1, o);
        }
        if (lane < 4) {
            atomicAdd(stats + n, s0);
            atomicAdd(stats + n + 1, s1);
            atomicAdd(stats + DD + n, q0);
            atomicAdd(stats + DD + n + 1, q1);
        }
    }
}

// ======================= BatchNorm normalize =======================

__global__ void bn_norm_kernel(const float* __restrict__ gamma,
                               const float* __restrict__ beta,
                               float* __restrict__ outp, int write_out, int layer) {
    __shared__ float scale_s[DD];
    __shared__ float shift_s[DD];
    if (threadIdx.x < DD) {
        int c = threadIdx.x;
        const float* stats = d_stats3 + layer * 2 * DD;
        float mu = stats[c] * (1.0f / NN);
        float var = stats[DD + c] * (1.0f / NN) - mu * mu;
        float sc = __ldg(gamma + c) * rsqrtf(var + EPS);
        scale_s[c] = sc;
        shift_s[c] = __ldg(beta + c) - mu * sc;
    }
    __syncthreads();
    float* dstp = write_out ? outp : d_h;
    size_t i = (size_t)blockIdx.x * blockDim.x + threadIdx.x;
    if (i >= (size_t)NN * DD / 4) return;
    int col = (int)((i * 4) & (DD - 1));
    float4 v = reinterpret_cast<const float4*>(d_acc)[i];
    float4 o;
    o.x = v.x * scale_s[col + 0] + shift_s[col + 0];
    o.y = v.y * scale_s[col + 1] + shift_s[col + 1];
    o.z = v.z * scale_s[col + 2] + shift_s[col + 2];
    o.w = v.w * scale_s[col + 3] + shift_s[col + 3];
    reinterpret_cast<float4*>(dstp)[i] = o;
}

// ======================= launch =======================

extern "C" void kernel_launch(void* const* d_in, const int* in_sizes, int n_in,
                              void* d_out, int out_size) {
    const float* x     = (const float*)d_in[0];
    const int*   src   = (const int*)d_in[1];
    const int*   dst   = (const int*)d_in[2];
    const float* Ws    = (const float*)d_in[3];
    const float* Wn    = (const float*)d_in[4];
    const float* bias  = (const float*)d_in[5];
    const float* gamma = (const float*)d_in[6];
    const float* beta  = (const float*)d_in[7];
    float* out = (float*)d_out;

    cudaFuncSetAttribute(gemm_merged_kernel,
                         cudaFuncAttributeMaxDynamicSharedMemorySize, SMEM_BYTES);

    {
        int n = NL * NET * 2 * DD * DD;
        wt_prep_kernel<<<(n + 255) / 256, 256>>>(Ws, Wn);
    }
    {
        zero_cnt_kernel<<<(NROWS + 255) / 256, 256>>>();
        int ne = NET * NE;
        deg_count_kernel<<<(ne + 255) / 256, 256>>>(dst);
        scan1_kernel<<<SCAN_BLK, 256>>>();
        scan2_kernel<<<1, 512>>>();
        scan3_kernel<<<SCAN_BLK, 256>>>();
        permute_kernel<<<(ne + 255) / 256, 256>>>(src, dst);
    }

    const int gemm_blocks = (NN + 127) / 128;
    const int gather_blocks = (NROWS * 32 + 255) / 256;
    const int bn4_blocks = (NN * DD / 4 + 255) / 256;

    for (int l = 0; l < NL; l++) {
        int use_x = (l == 0);
        int do_relu = (l < NL - 1);
        gather_kernel<<<gather_blocks, 256>>>(x, use_x);
        gemm_merged_kernel<<<gemm_blocks, 256, SMEM_BYTES>>>(
            x, use_x, l, bias + (size_t)l * NET * DD, do_relu);
        bn_norm_kernel<<<bn4_blocks, 256>>>(gamma + l * DD, beta + l * DD,
                                            out, (l == NL - 1), l);
    }
}

// round 15
// speedup vs baseline: 1.7958x; 1.0884x over previous
#include <cuda_runtime.h>
#include <cstdint>

#define NN 100000
#define NE 600000
#define NET 3
#define NL 3
#define DD 128
#define EPS 1e-5f
#define NROWS (NET * NN)
#define SCAN_BLK 293

// ---------------- static device scratch (device-code access ONLY) ----------------
__device__ float d_h[(size_t)NN * DD];
__device__ float d_neigh[(size_t)NET * NN * DD];
__device__ float d_acc[(size_t)NN * DD];
__device__ float d_invdeg[NROWS];
__device__ float d_stats3[NL * 2 * DD];
__device__ float d_Wt[(size_t)NL * NET * 2 * DD * DD];  // W^T tf32: [l][e][sel][n][kk]
__device__ int   d_cnt[NROWS];
__device__ int   d_rowoff[NROWS + 1];
__device__ int   d_bsums[512];
__device__ int   d_esrc[NET * NE];

// ======================= prep: CSR build =======================

__global__ void zero_cnt_kernel() {
    int i = blockIdx.x * blockDim.x + threadIdx.x;
    if (i < NROWS) d_cnt[i] = 0;
    if (i < NL * 2 * DD) d_stats3[i] = 0.f;
}
__global__ void deg_count_kernel(const int* __restrict__ dst) {
    int idx = blockIdx.x * blockDim.x + threadIdx.x;
    if (idx >= NET * NE) return;
    int k = idx / NE;
    atomicAdd(&d_cnt[k * NN + __ldg(dst + idx)], 1);
}
__global__ void scan1_kernel() {
    int base = blockIdx.x * 1024;
    int t = threadIdx.x;
    int sum = 0;
#pragma unroll
    for (int j = 0; j < 4; j++) {
        int i = base + t * 4 + j;
        if (i < NROWS) sum += d_cnt[i];
    }
#pragma unroll
    for (int o = 16; o; o >>= 1) sum += __shfl_down_sync(0xFFFFFFFFu, sum, o);
    __shared__ int ws[8];
    if ((t & 31) == 0) ws[t >> 5] = sum;
    __syncthreads();
    if (t == 0) {
        int v = 0;
#pragma unroll
        for (int i = 0; i < 8; i++) v += ws[i];
        d_bsums[blockIdx.x] = v;
    }
}
__global__ void scan2_kernel() {
    __shared__ int s[512];
    int t = threadIdx.x;
    int orig = (t < SCAN_BLK) ? d_bsums[t] : 0;
    s[t] = orig;
    __syncthreads();
#pragma unroll
    for (int o = 1; o < 512; o <<= 1) {
        int v = (t >= o) ? s[t - o] : 0;
        __syncthreads();
        s[t] += v;
        __syncthreads();
    }
    if (t < SCAN_BLK) d_bsums[t] = s[t] - orig;
}
__global__ void scan3_kernel() {
    int base = blockIdx.x * 1024;
    int t = threadIdx.x, lane = t & 31, warp = t >> 5;
    int vals[4];
    int tsum = 0;
#pragma unroll
    for (int j = 0; j < 4; j++) {
        int i = base + t * 4 + j;
        vals[j] = (i < NROWS) ? d_cnt[i] : 0;
        tsum += vals[j];
    }
    int inc = tsum;
#pragma unroll
    for (int o = 1; o < 32; o <<= 1) {
        int v = __shfl_up_sync(0xFFFFFFFFu, inc, o);
        if (lane >= o) inc += v;
    }
    int texcl = inc - tsum;
    __shared__ int wsum[8];
    if (lane == 31) wsum[warp] = inc;
    __syncthreads();
    __shared__ int woff[8];
    if (t == 0) {
        int a = 0;
#pragma unroll
        for (int i = 0; i < 8; i++) { woff[i] = a; a += wsum[i]; }
    }
    __syncthreads();
    int run = d_bsums[blockIdx.x] + woff[warp] + texcl;
#pragma unroll
    for (int j = 0; j < 4; j++) {
        int i = base + t * 4 + j;
        if (i < NROWS) {
            d_rowoff[i] = run;
            d_invdeg[i] = 1.0f / fmaxf((float)vals[j], 1.0f);
            d_cnt[i] = 0;
            run += vals[j];
        }
    }
    if (blockIdx.x == 0 && t == 0) d_rowoff[NROWS] = NET * NE;
}
__global__ void permute_kernel(const int* __restrict__ src, const int* __restrict__ dst) {
    int idx = blockIdx.x * blockDim.x + threadIdx.x;
    if (idx >= NET * NE) return;
    int k = idx / NE;
    int g = k * NN + __ldg(dst + idx);
    int pos = d_rowoff[g] + atomicAdd(&d_cnt[g], 1);
    d_esrc[pos] = __ldg(src + idx);
}

__device__ __forceinline__ uint32_t f2tf32(float x) {
    uint32_t r;
    asm("cvt.rna.tf32.f32 %0, %1;" : "=r"(r) : "f"(x));
    return r;
}

// W^T + tf32: d_Wt[(m*2+sel)*16384 + n*128 + kk] = tf32(W[m][sel][kk][n])
// layer-2 (m==6) self slot additionally holds merged sum_e(Ws_e) since last layer has no relu
__global__ void wt_prep_kernel(const float* __restrict__ Ws, const float* __restrict__ Wn) {
    int i = blockIdx.x * blockDim.x + threadIdx.x;
    if (i >= NL * NET * 2 * DD * DD) return;
    int kk = i & 127;
    int n = (i >> 7) & 127;
    int sel = (i >> 14) & 1;
    int m = i >> 15;
    float v;
    if (m == 2 * NET && sel == 0) {
        v = __ldg(Ws + (size_t)6 * 16384 + kk * DD + n)
          + __ldg(Ws + (size_t)7 * 16384 + kk * DD + n)
          + __ldg(Ws + (size_t)8 * 16384 + kk * DD + n);
    } else {
        v = __ldg((sel ? Wn : Ws) + (size_t)m * 16384 + kk * DD + n);
    }
    d_Wt[i] = __uint_as_float(f2tf32(v));
}

// ======================= gather (CSR mean, round-7 style) =======================
__global__ void gather_kernel(const float* __restrict__ x, int use_x) {
    const float* hin = use_x ? x : d_h;
    int w = (blockIdx.x * blockDim.x + threadIdx.x) >> 5;
    int lane = threadIdx.x & 31;
    if (w >= NROWS) return;
    int o0 = __ldg(&d_rowoff[w]);
    int o1 = __ldg(&d_rowoff[w + 1]);
    float4 a = make_float4(0.f, 0.f, 0.f, 0.f);
    int s = (o0 < o1) ? __ldg(&d_esrc[o0]) : 0;
    for (int e = o0; e < o1; e++) {
        int sn = (e + 1 < o1) ? __ldg(&d_esrc[e + 1]) : 0;
        float4 v = __ldg(reinterpret_cast<const float4*>(hin + (size_t)s * DD) + lane);
        a.x += v.x; a.y += v.y; a.z += v.z; a.w += v.w;
        s = sn;
    }
    float sc = d_invdeg[w];
    a.x *= sc; a.y *= sc; a.z *= sc; a.w *= sc;
    reinterpret_cast<float4*>(d_neigh)[(size_t)w * 32 + lane] = a;
}

// ======================= templated tf32 mma GEMM (fully unrolled static schedule) =======================

#define ASTRIDE 36
#define ATILE (128 * ASTRIDE)
#define SMEM_BYTES (4 * ATILE * 4)

__device__ __forceinline__ void ldsm4(uint32_t* r, uint32_t addr) {
    asm volatile("ldmatrix.sync.aligned.m8n8.x4.shared.b16 {%0,%1,%2,%3}, [%4];"
                 : "=r"(r[0]), "=r"(r[1]), "=r"(r[2]), "=r"(r[3]) : "r"(addr));
}
__device__ __forceinline__ void mma8(float* c, const uint32_t* a, uint32_t b0, uint32_t b1) {
    asm volatile("mma.sync.aligned.m16n8k8.row.col.f32.tf32.tf32.f32 "
                 "{%0,%1,%2,%3}, {%4,%5,%6,%7}, {%8,%9}, {%0,%1,%2,%3};"
                 : "+f"(c[0]), "+f"(c[1]), "+f"(c[2]), "+f"(c[3])
                 : "r"(a[0]), "r"(a[1]), "r"(a[2]), "r"(a[3]), "r"(b0), "r"(b1));
}

__device__ __forceinline__ void ldgA(float4* ra, const float* __restrict__ src,
                                     int m0, int koff, int tid) {
#pragma unroll
    for (int t = 0; t < 4; t++) {
        int c = tid + t * 256;
        int gr = m0 + (c >> 3);
        ra[t] = (gr < NN)
            ? __ldg(reinterpret_cast<const float4*>(src + (size_t)gr * DD + koff) + (c & 7))
            : make_float4(0.f, 0.f, 0.f, 0.f);
    }
}
__device__ __forceinline__ void ldgB(float4* rb, const float* __restrict__ W,
                                     int koff, int tid) {
#pragma unroll
    for (int t = 0; t < 4; t++) {
        int c = tid + t * 256;
        rb[t] = __ldg(reinterpret_cast<const float4*>(W + (size_t)(c >> 3) * DD + koff) + (c & 7));
    }
}
__device__ __forceinline__ void stsA(float* As, const float4* ra, int tid) {
#pragma unroll
    for (int t = 0; t < 4; t++) {
        int c = tid + t * 256;
        uint4 u;
        u.x = f2tf32(ra[t].x); u.y = f2tf32(ra[t].y);
        u.z = f2tf32(ra[t].z); u.w = f2tf32(ra[t].w);
        *reinterpret_cast<uint4*>(As + (c >> 3) * ASTRIDE + (c & 7) * 4) = u;
    }
}
__device__ __forceinline__ void stsB(float* Bs, const float4* rb, int tid) {
#pragma unroll
    for (int t = 0; t < 4; t++) {
        int c = tid + t * 256;
        *reinterpret_cast<float4*>(Bs + (c >> 3) * ASTRIDE + (c & 7) * 4) = rb[t];
    }
}

template<bool MERGED>
__global__ void __launch_bounds__(256)
gemm_merged_kernel(const float* __restrict__ x, int use_x, int layer,
                   const float* __restrict__ bias, int do_relu) {
    extern __shared__ float sm[];
    float* Abuf[2] = { sm, sm + ATILE };
    float* Bbuf[2] = { sm + 2 * ATILE, sm + 3 * ATILE };
    uint32_t smb = (uint32_t)__cvta_generic_to_shared(sm);
    uint32_t asu[2] = { smb, smb + ATILE * 4 };
    uint32_t bsu[2] = { smb + 2 * ATILE * 4, smb + 3 * ATILE * 4 };

    const float* hin = use_x ? x : d_h;
    const float* Wl = d_Wt + (size_t)layer * NET * 2 * DD * DD;
    float* stats = d_stats3 + layer * 2 * DD;
    constexpr int NT = MERGED ? 16 : 24;

    int tid = threadIdx.x, lane = tid & 31, wid = tid >> 5;
    int wm = wid & 3, wn = wid >> 2;
    int m0 = blockIdx.x * 128;

    uint32_t aoffb[2];
#pragma unroll
    for (int mf = 0; mf < 2; mf++)
        aoffb[mf] = ((wm * 32 + mf * 16 + (lane & 15)) * ASTRIDE + (lane >> 4) * 4) * 4;
    uint32_t boffb[4];
#pragma unroll
    for (int nf2 = 0; nf2 < 4; nf2++) {
        int n = wn * 64 + nf2 * 16 + (lane & 7) + ((lane >> 4) << 3);
        boffb[nf2] = (n * ASTRIDE + ((lane >> 3) & 1) * 4) * 4;
    }

    float facc[2][8][4], acc[2][8][4];
#pragma unroll
    for (int i = 0; i < 2; i++)
#pragma unroll
        for (int j = 0; j < 8; j++)
#pragma unroll
            for (int e = 0; e < 4; e++) { facc[i][j][e] = 0.f; acc[i][j][e] = 0.f; }

    float4 ra[4], rb[4];
    ldgA(ra, hin, m0, 0, tid);
    ldgB(rb, Wl, 0, tid);
    stsA(Abuf[0], ra, tid);
    stsB(Bbuf[0], rb, tid);
    __syncthreads();

#pragma unroll
    for (int t = 0; t < NT; t++) {
        const int cur = t & 1;
        if (t < NT - 1) {
            const int tn = t + 1;
            const float* A;
            const float* W;
            if (!MERGED) {
                const int pn = tn >> 2;
                A = (pn & 1) ? (d_neigh + (size_t)(pn >> 1) * NN * DD) : hin;
                W = Wl + (size_t)pn * 16384;
            } else {
                const int p = tn >> 2;
                A = (p == 0) ? hin : (d_neigh + (size_t)(p - 1) * NN * DD);
                W = (p == 0) ? Wl : (Wl + (size_t)((p - 1) * 2 + 1) * 16384);
            }
            ldgA(ra, A, m0, (tn & 3) * 32, tid);
            ldgB(rb, W, (tn & 3) * 32, tid);
        }
#pragma unroll
        for (int ks = 0; ks < 4; ks++) {
            uint32_t af[2][4];
            ldsm4(af[0], asu[cur] + aoffb[0] + ks * 32);
            ldsm4(af[1], asu[cur] + aoffb[1] + ks * 32);
            uint32_t bf[4][4];
#pragma unroll
            for (int nf2 = 0; nf2 < 4; nf2++)
                ldsm4(bf[nf2], bsu[cur] + boffb[nf2] + ks * 32);
#pragma unroll
            for (int mf = 0; mf < 2; mf++)
#pragma unroll
                for (int nf = 0; nf < 8; nf++) {
                    int q = (nf & 1) * 2;
                    mma8(acc[mf][nf], af[mf], bf[nf >> 1][q], bf[nf >> 1][q + 1]);
                }
        }
        const bool fold = MERGED ? (t == NT - 1) : ((t & 7) == 7);
        if (fold) {
#pragma unroll
            for (int nf = 0; nf < 8; nf++) {
                int n = wn * 64 + nf * 8 + ((lane & 3) << 1);
                float b0, b1;
                if (MERGED) {
                    b0 = __ldg(bias + n) + __ldg(bias + DD + n) + __ldg(bias + 2 * DD + n);
                    b1 = __ldg(bias + n + 1) + __ldg(bias + DD + n + 1) + __ldg(bias + 2 * DD + n + 1);
                } else {
                    const float* be = bias + (t >> 3) * DD;
                    b0 = __ldg(be + n); b1 = __ldg(be + n + 1);
                }
#pragma unroll
                for (int mf = 0; mf < 2; mf++) {
                    float v0 = acc[mf][nf][0] + b0, v1 = acc[mf][nf][1] + b1;
                    float v2 = acc[mf][nf][2] + b0, v3 = acc[mf][nf][3] + b1;
                    if (do_relu) {
                        v0 = fmaxf(v0, 0.f); v1 = fmaxf(v1, 0.f);
                        v2 = fmaxf(v2, 0.f); v3 = fmaxf(v3, 0.f);
                    }
                    facc[mf][nf][0] += v0; facc[mf][nf][1] += v1;
                    facc[mf][nf][2] += v2; facc[mf][nf][3] += v3;
                    acc[mf][nf][0] = 0.f; acc[mf][nf][1] = 0.f;
                    acc[mf][nf][2] = 0.f; acc[mf][nf][3] = 0.f;
                }
            }
        }
        if (t < NT - 1) {
            __syncthreads();
            stsA(Abuf[1 - cur], ra, tid);
            stsB(Bbuf[1 - cur], rb, tid);
            __syncthreads();
        }
    }

    int r0 = m0 + wm * 32 + (lane >> 2);
    int rr[2] = { r0, r0 + 16 };
#pragma unroll
    for (int nf = 0; nf < 8; nf++) {
        int n = wn * 64 + nf * 8 + ((lane & 3) << 1);
        float s0 = 0.f, s1 = 0.f, q0 = 0.f, q1 = 0.f;
#pragma unroll
        for (int mf = 0; mf < 2; mf++) {
            int r = rr[mf];
            float v0 = facc[mf][nf][0], v1 = facc[mf][nf][1];
            float v2 = facc[mf][nf][2], v3 = facc[mf][nf][3];
            if (r < NN) {
                *reinterpret_cast<float2*>(d_acc + (size_t)r * DD + n) = make_float2(v0, v1);
                s0 += v0; s1 += v1;
                q0 = fmaf(v0, v0, q0); q1 = fmaf(v1, v1, q1);
            }
            if (r + 8 < NN) {
                *reinterpret_cast<float2*>(d_acc + (size_t)(r + 8) * DD + n) = make_float2(v2, v3);
                s0 += v2; s1 += v3;
                q0 = fmaf(v2, v2, q0); q1 = fmaf(v3, v3, q1);
            }
        }
#pragma unroll
        for (int o = 4; o < 32; o <<= 1) {
            s0 += __shfl_xor_sync(0xFFFFFFFFu, s0, o);
            s1 += __shfl_xor_sync(0xFFFFFFFFu, s1, o);
            q0 += __shfl_xor_sync(0xFFFFFFFFu, q0, o);
            q1 += __shfl_xor_sync(0xFFFFFFFFu, q1, o);
        }
        if (lane < 4) {
            atomicAdd(stats + n, s0);
            atomicAdd(stats + n + 1, s1);
            atomicAdd(stats + DD + n, q0);
            atomicAdd(stats + DD + n + 1, q1);
        }
    }
}

// ======================= BatchNorm normalize =======================

__global__ void bn_norm_kernel(const float* __restrict__ gamma,
                               const float* __restrict__ beta,
                               float* __restrict__ outp, int write_out, int layer) {
    __shared__ float scale_s[DD];
    __shared__ float shift_s[DD];
    if (threadIdx.x < DD) {
        int c = threadIdx.x;
        const float* stats = d_stats3 + layer * 2 * DD;
        float mu = stats[c] * (1.0f / NN);
        float var = stats[DD + c] * (1.0f / NN) - mu * mu;
        float sc = __ldg(gamma + c) * rsqrtf(var + EPS);
        scale_s[c] = sc;
        shift_s[c] = __ldg(beta + c) - mu * sc;
    }
    __syncthreads();
    float* dstp = write_out ? outp : d_h;
    size_t i = (size_t)blockIdx.x * blockDim.x + threadIdx.x;
    if (i >= (size_t)NN * DD / 4) return;
    int col = (int)((i * 4) & (DD - 1));
    float4 v = reinterpret_cast<const float4*>(d_acc)[i];
    float4 o;
    o.x = v.x * scale_s[col + 0] + shift_s[col + 0];
    o.y = v.y * scale_s[col + 1] + shift_s[col + 1];
    o.z = v.z * scale_s[col + 2] + shift_s[col + 2];
    o.w = v.w * scale_s[col + 3] + shift_s[col + 3];
    reinterpret_cast<float4*>(dstp)[i] = o;
}

// ======================= launch =======================

extern "C" void kernel_launch(void* const* d_in, const int* in_sizes, int n_in,
                              void* d_out, int out_size) {
    const float* x     = (const float*)d_in[0];
    const int*   src   = (const int*)d_in[1];
    const int*   dst   = (const int*)d_in[2];
    const float* Ws    = (const float*)d_in[3];
    const float* Wn    = (const float*)d_in[4];
    const float* bias  = (const float*)d_in[5];
    const float* gamma = (const float*)d_in[6];
    const float* beta  = (const float*)d_in[7];
    float* out = (float*)d_out;

    cudaFuncSetAttribute(gemm_merged_kernel<false>,
                         cudaFuncAttributeMaxDynamicSharedMemorySize, SMEM_BYTES);
    cudaFuncSetAttribute(gemm_merged_kernel<true>,
                         cudaFuncAttributeMaxDynamicSharedMemorySize, SMEM_BYTES);

    {
        int n = NL * NET * 2 * DD * DD;
        wt_prep_kernel<<<(n + 255) / 256, 256>>>(Ws, Wn);
    }
    {
        zero_cnt_kernel<<<(NROWS + 255) / 256, 256>>>();
        int ne = NET * NE;
        deg_count_kernel<<<(ne + 255) / 256, 256>>>(dst);
        scan1_kernel<<<SCAN_BLK, 256>>>();
        scan2_kernel<<<1, 512>>>();
        scan3_kernel<<<SCAN_BLK, 256>>>();
        permute_kernel<<<(ne + 255) / 256, 256>>>(src, dst);
    }

    const int gemm_blocks = (NN + 127) / 128;
    const int gather_blocks = (NROWS * 32 + 255) / 256;
    const int bn4_blocks = (NN * DD / 4 + 255) / 256;

    for (int l = 0; l < NL; l++) {
        int use_x = (l == 0);
        int do_relu = (l < NL - 1);
        gather_kernel<<<gather_blocks, 256>>>(x, use_x);
        if (l == 2)
            gemm_merged_kernel<true><<<gemm_blocks, 256, SMEM_BYTES>>>(
                x, 0, l, bias + (size_t)l * NET * DD, 0);
        else
            gemm_merged_kernel<false><<<gemm_blocks, 256, SMEM_BYTES>>>(
                x, use_x, l, bias + (size_t)l * NET * DD, do_relu);
        bn_norm_kernel<<<bn4_blocks, 256>>>(gamma + l * DD, beta + l * DD,
                                            out, (l == NL - 1), l);
    }
}

// round 16
// speedup vs baseline: 1.9780x; 1.1015x over previous
#include <cuda_runtime.h>
#include <cstdint>

#define NN 100000
#define NE 600000
#define NET 3
#define NL 3
#define DD 128
#define EPS 1e-5f
#define NROWS (NET * NN)
#define SCAN_BLK 293

// ---------------- static device scratch (device-code access ONLY) ----------------
__device__ float d_h[(size_t)NN * DD];                  // fp32 hidden (gather input)
__device__ float d_hr[(size_t)NN * DD];                 // tf32-rounded hidden (GEMM A input)
__device__ float d_neigh[(size_t)NET * NN * DD];        // tf32-rounded neighbor means
__device__ float d_acc[(size_t)NN * DD];
__device__ float d_invdeg[NROWS];
__device__ float d_stats3[NL * 2 * DD];
__device__ float d_Wt[(size_t)NL * NET * 2 * DD * DD];  // W^T tf32: [l][e][sel][n][kk]
__device__ int   d_cnt[NROWS];
__device__ int   d_rowoff[NROWS + 1];
__device__ int   d_bsums[512];
__device__ int   d_esrc[NET * NE];

// ======================= prep: CSR build =======================

__global__ void zero_cnt_kernel() {
    int i = blockIdx.x * blockDim.x + threadIdx.x;
    if (i < NROWS) d_cnt[i] = 0;
    if (i < NL * 2 * DD) d_stats3[i] = 0.f;
}
__global__ void deg_count_kernel(const int* __restrict__ dst) {
    int idx = blockIdx.x * blockDim.x + threadIdx.x;
    if (idx >= NET * NE) return;
    int k = idx / NE;
    atomicAdd(&d_cnt[k * NN + __ldg(dst + idx)], 1);
}
__global__ void scan1_kernel() {
    int base = blockIdx.x * 1024;
    int t = threadIdx.x;
    int sum = 0;
#pragma unroll
    for (int j = 0; j < 4; j++) {
        int i = base + t * 4 + j;
        if (i < NROWS) sum += d_cnt[i];
    }
#pragma unroll
    for (int o = 16; o; o >>= 1) sum += __shfl_down_sync(0xFFFFFFFFu, sum, o);
    __shared__ int ws[8];
    if ((t & 31) == 0) ws[t >> 5] = sum;
    __syncthreads();
    if (t == 0) {
        int v = 0;
#pragma unroll
        for (int i = 0; i < 8; i++) v += ws[i];
        d_bsums[blockIdx.x] = v;
    }
}
__global__ void scan2_kernel() {
    __shared__ int s[512];
    int t = threadIdx.x;
    int orig = (t < SCAN_BLK) ? d_bsums[t] : 0;
    s[t] = orig;
    __syncthreads();
#pragma unroll
    for (int o = 1; o < 512; o <<= 1) {
        int v = (t >= o) ? s[t - o] : 0;
        __syncthreads();
        s[t] += v;
        __syncthreads();
    }
    if (t < SCAN_BLK) d_bsums[t] = s[t] - orig;
}
__global__ void scan3_kernel() {
    int base = blockIdx.x * 1024;
    int t = threadIdx.x, lane = t & 31, warp = t >> 5;
    int vals[4];
    int tsum = 0;
#pragma unroll
    for (int j = 0; j < 4; j++) {
        int i = base + t * 4 + j;
        vals[j] = (i < NROWS) ? d_cnt[i] : 0;
        tsum += vals[j];
    }
    int inc = tsum;
#pragma unroll
    for (int o = 1; o < 32; o <<= 1) {
        int v = __shfl_up_sync(0xFFFFFFFFu, inc, o);
        if (lane >= o) inc += v;
    }
    int texcl = inc - tsum;
    __shared__ int wsum[8];
    if (lane == 31) wsum[warp] = inc;
    __syncthreads();
    __shared__ int woff[8];
    if (t == 0) {
        int a = 0;
#pragma unroll
        for (int i = 0; i < 8; i++) { woff[i] = a; a += wsum[i]; }
    }
    __syncthreads();
    int run = d_bsums[blockIdx.x] + woff[warp] + texcl;
#pragma unroll
    for (int j = 0; j < 4; j++) {
        int i = base + t * 4 + j;
        if (i < NROWS) {
            d_rowoff[i] = run;
            d_invdeg[i] = 1.0f / fmaxf((float)vals[j], 1.0f);
            d_cnt[i] = 0;
            run += vals[j];
        }
    }
    if (blockIdx.x == 0 && t == 0) d_rowoff[NROWS] = NET * NE;
}
__global__ void permute_kernel(const int* __restrict__ src, const int* __restrict__ dst) {
    int idx = blockIdx.x * blockDim.x + threadIdx.x;
    if (idx >= NET * NE) return;
    int k = idx / NE;
    int g = k * NN + __ldg(dst + idx);
    int pos = d_rowoff[g] + atomicAdd(&d_cnt[g], 1);
    d_esrc[pos] = __ldg(src + idx);
}

__device__ __forceinline__ uint32_t f2tf32(float x) {
    uint32_t r;
    asm("cvt.rna.tf32.f32 %0, %1;" : "=r"(r) : "f"(x));
    return r;
}

// W^T + tf32; layer-2 (m==6) self slot holds merged sum_e(Ws_e) (last layer has no relu)
__global__ void wt_prep_kernel(const float* __restrict__ Ws, const float* __restrict__ Wn) {
    int i = blockIdx.x * blockDim.x + threadIdx.x;
    if (i >= NL * NET * 2 * DD * DD) return;
    int kk = i & 127;
    int n = (i >> 7) & 127;
    int sel = (i >> 14) & 1;
    int m = i >> 15;
    float v;
    if (m == 2 * NET && sel == 0) {
        v = __ldg(Ws + (size_t)6 * 16384 + kk * DD + n)
          + __ldg(Ws + (size_t)7 * 16384 + kk * DD + n)
          + __ldg(Ws + (size_t)8 * 16384 + kk * DD + n);
    } else {
        v = __ldg((sel ? Wn : Ws) + (size_t)m * 16384 + kk * DD + n);
    }
    d_Wt[i] = __uint_as_float(f2tf32(v));
}

// x -> tf32-rounded d_hr (layer-0 GEMM A source)
__global__ void xr_prep_kernel(const float* __restrict__ x) {
    int i = blockIdx.x * blockDim.x + threadIdx.x;
    if (i >= NN * 32) return;
    float4 v = __ldg(reinterpret_cast<const float4*>(x) + i);
    uint4 u;
    u.x = f2tf32(v.x); u.y = f2tf32(v.y); u.z = f2tf32(v.z); u.w = f2tf32(v.w);
    reinterpret_cast<uint4*>(d_hr)[i] = u;
}

// ======================= gather (CSR mean; output tf32-rounded) =======================
__global__ void gather_kernel(const float* __restrict__ x, int use_x) {
    const float* hin = use_x ? x : d_h;
    int w = (blockIdx.x * blockDim.x + threadIdx.x) >> 5;
    int lane = threadIdx.x & 31;
    if (w >= NROWS) return;
    int o0 = __ldg(&d_rowoff[w]);
    int o1 = __ldg(&d_rowoff[w + 1]);
    float4 a = make_float4(0.f, 0.f, 0.f, 0.f);
    int s = (o0 < o1) ? __ldg(&d_esrc[o0]) : 0;
    for (int e = o0; e < o1; e++) {
        int sn = (e + 1 < o1) ? __ldg(&d_esrc[e + 1]) : 0;
        float4 v = __ldg(reinterpret_cast<const float4*>(hin + (size_t)s * DD) + lane);
        a.x += v.x; a.y += v.y; a.z += v.z; a.w += v.w;
        s = sn;
    }
    float sc = d_invdeg[w];
    uint4 u;
    u.x = f2tf32(a.x * sc); u.y = f2tf32(a.y * sc);
    u.z = f2tf32(a.z * sc); u.w = f2tf32(a.w * sc);
    reinterpret_cast<uint4*>(d_neigh)[(size_t)w * 32 + lane] = u;
}

// ======================= cp.async 4-stage tf32 mma GEMM =======================

#define ASTRIDE 36
#define ATILE (128 * ASTRIDE)
#define NSTAGE 4
#define SMEM_BYTES (2 * NSTAGE * ATILE * 4)   // 147456 B

__device__ __forceinline__ void ldsm4(uint32_t* r, uint32_t addr) {
    asm volatile("ldmatrix.sync.aligned.m8n8.x4.shared.b16 {%0,%1,%2,%3}, [%4];"
                 : "=r"(r[0]), "=r"(r[1]), "=r"(r[2]), "=r"(r[3]) : "r"(addr));
}
__device__ __forceinline__ void mma8(float* c, const uint32_t* a, uint32_t b0, uint32_t b1) {
    asm volatile("mma.sync.aligned.m16n8k8.row.col.f32.tf32.tf32.f32 "
                 "{%0,%1,%2,%3}, {%4,%5,%6,%7}, {%8,%9}, {%0,%1,%2,%3};"
                 : "+f"(c[0]), "+f"(c[1]), "+f"(c[2]), "+f"(c[3])
                 : "r"(a[0]), "r"(a[1]), "r"(a[2]), "r"(a[3]), "r"(b0), "r"(b1));
}
__device__ __forceinline__ void cpa16(uint32_t dst, const float* src, int nbytes) {
    asm volatile("cp.async.cg.shared.global [%0], [%1], 16, %2;"
                 :: "r"(dst), "l"(src), "r"(nbytes));
}
#define CP_COMMIT() asm volatile("cp.async.commit_group;" ::: "memory")
#define CP_WAIT2()  asm volatile("cp.async.wait_group 2;" ::: "memory")

// issue one 128x32 A tile (row-bounded) + one 128x32 B tile via cp.async
__device__ __forceinline__ void issue_tile(uint32_t a_u, uint32_t b_u,
                                           const float* __restrict__ Asrc, int m0, int koff,
                                           const float* __restrict__ W, int tid) {
#pragma unroll
    for (int i = 0; i < 4; i++) {
        int c = tid + i * 256;          // 0..1023
        int row = c >> 3, q = c & 7;
        int gr = m0 + row;
        cpa16(a_u + (uint32_t)(row * ASTRIDE + q * 4) * 4,
              Asrc + (size_t)gr * DD + koff + q * 4, (gr < NN) ? 16 : 0);
    }
#pragma unroll
    for (int i = 0; i < 4; i++) {
        int c = tid + i * 256;
        int row = c >> 3, q = c & 7;
        cpa16(b_u + (uint32_t)(row * ASTRIDE + q * 4) * 4,
              W + (size_t)row * DD + koff + q * 4, 16);
    }
}

template<bool MERGED>
__global__ void __launch_bounds__(256)
gemm_ca_kernel(int layer, const float* __restrict__ bias, int do_relu) {
    extern __shared__ float sm[];
    uint32_t smb = (uint32_t)__cvta_generic_to_shared(sm);
    uint32_t asu[NSTAGE], bsu[NSTAGE];
#pragma unroll
    for (int s = 0; s < NSTAGE; s++) {
        asu[s] = smb + (uint32_t)s * ATILE * 4;
        bsu[s] = smb + (uint32_t)(NSTAGE + s) * ATILE * 4;
    }

    const float* Wl = d_Wt + (size_t)layer * NET * 2 * DD * DD;
    float* stats = d_stats3 + layer * 2 * DD;
    constexpr int NT = MERGED ? 16 : 24;

    int tid = threadIdx.x, lane = tid & 31, wid = tid >> 5;
    int wm = wid & 3, wn = wid >> 2;
    int m0 = blockIdx.x * 128;

    uint32_t aoffb[2];
#pragma unroll
    for (int mf = 0; mf < 2; mf++)
        aoffb[mf] = ((wm * 32 + mf * 16 + (lane & 15)) * ASTRIDE + (lane >> 4) * 4) * 4;
    uint32_t boffb[4];
#pragma unroll
    for (int nf2 = 0; nf2 < 4; nf2++) {
        int n = wn * 64 + nf2 * 16 + (lane & 7) + ((lane >> 4) << 3);
        boffb[nf2] = (n * ASTRIDE + ((lane >> 3) & 1) * 4) * 4;
    }

    float facc[2][8][4], acc[2][8][4];
#pragma unroll
    for (int i = 0; i < 2; i++)
#pragma unroll
        for (int j = 0; j < 8; j++)
#pragma unroll
            for (int e = 0; e < 4; e++) { facc[i][j][e] = 0.f; acc[i][j][e] = 0.f; }

    // ---- prologue: issue tiles 0..2 ----
#pragma unroll
    for (int t = 0; t < NSTAGE - 1; t++) {
        const float* A;
        const float* W;
        if (!MERGED) {
            const int pn = t >> 2;
            A = (pn & 1) ? (d_neigh + (size_t)(pn >> 1) * NN * DD) : d_hr;
            W = Wl + (size_t)pn * 16384;
        } else {
            const int p = t >> 2;
            A = (p == 0) ? d_hr : (d_neigh + (size_t)(p - 1) * NN * DD);
            W = (p == 0) ? Wl : (Wl + (size_t)((p - 1) * 2 + 1) * 16384);
        }
        issue_tile(asu[t], bsu[t], A, m0, (t & 3) * 32, W, tid);
        CP_COMMIT();
    }

#pragma unroll
    for (int t = 0; t < NT; t++) {
        const int cur = t & (NSTAGE - 1);
        CP_WAIT2();
        __syncthreads();   // tile t visible; all warps done with tile t-1's buffer
        {
            const int tn = t + NSTAGE - 1;
            if (tn < NT) {
                const float* A;
                const float* W;
                if (!MERGED) {
                    const int pn = tn >> 2;
                    A = (pn & 1) ? (d_neigh + (size_t)(pn >> 1) * NN * DD) : d_hr;
                    W = Wl + (size_t)pn * 16384;
                } else {
                    const int p = tn >> 2;
                    A = (p == 0) ? d_hr : (d_neigh + (size_t)(p - 1) * NN * DD);
                    W = (p == 0) ? Wl : (Wl + (size_t)((p - 1) * 2 + 1) * 16384);
                }
                issue_tile(asu[tn & (NSTAGE - 1)], bsu[tn & (NSTAGE - 1)],
                           A, m0, (tn & 3) * 32, W, tid);
            }
            CP_COMMIT();   // always commit (possibly empty) to keep group count uniform
        }
#pragma unroll
        for (int ks = 0; ks < 4; ks++) {
            uint32_t af[2][4];
            ldsm4(af[0], asu[cur] + aoffb[0] + ks * 32);
            ldsm4(af[1], asu[cur] + aoffb[1] + ks * 32);
            uint32_t bf[4][4];
#pragma unroll
            for (int nf2 = 0; nf2 < 4; nf2++)
                ldsm4(bf[nf2], bsu[cur] + boffb[nf2] + ks * 32);
#pragma unroll
            for (int mf = 0; mf < 2; mf++)
#pragma unroll
                for (int nf = 0; nf < 8; nf++) {
                    int q = (nf & 1) * 2;
                    mma8(acc[mf][nf], af[mf], bf[nf >> 1][q], bf[nf >> 1][q + 1]);
                }
        }
        const bool fold = MERGED ? (t == NT - 1) : ((t & 7) == 7);
        if (fold) {
#pragma unroll
            for (int nf = 0; nf < 8; nf++) {
                int n = wn * 64 + nf * 8 + ((lane & 3) << 1);
                float b0, b1;
                if (MERGED) {
                    b0 = __ldg(bias + n) + __ldg(bias + DD + n) + __ldg(bias + 2 * DD + n);
                    b1 = __ldg(bias + n + 1) + __ldg(bias + DD + n + 1) + __ldg(bias + 2 * DD + n + 1);
                } else {
                    const float* be = bias + (t >> 3) * DD;
                    b0 = __ldg(be + n); b1 = __ldg(be + n + 1);
                }
#pragma unroll
                for (int mf = 0; mf < 2; mf++) {
                    float v0 = acc[mf][nf][0] + b0, v1 = acc[mf][nf][1] + b1;
                    float v2 = acc[mf][nf][2] + b0, v3 = acc[mf][nf][3] + b1;
                    if (do_relu) {
                        v0 = fmaxf(v0, 0.f); v1 = fmaxf(v1, 0.f);
                        v2 = fmaxf(v2, 0.f); v3 = fmaxf(v3, 0.f);
                    }
                    facc[mf][nf][0] += v0; facc[mf][nf][1] += v1;
                    facc[mf][nf][2] += v2; facc[mf][nf][3] += v3;
                    acc[mf][nf][0] = 0.f; acc[mf][nf][1] = 0.f;
                    acc[mf][nf][2] = 0.f; acc[mf][nf][3] = 0.f;
                }
            }
        }
    }

    // ---- epilogue: store + BN column stats ----
    int r0 = m0 + wm * 32 + (lane >> 2);
    int rr[2] = { r0, r0 + 16 };
#pragma unroll
    for (int nf = 0; nf < 8; nf++) {
        int n = wn * 64 + nf * 8 + ((lane & 3) << 1);
        float s0 = 0.f, s1 = 0.f, q0 = 0.f, q1 = 0.f;
#pragma unroll
        for (int mf = 0; mf < 2; mf++) {
            int r = rr[mf];
            float v0 = facc[mf][nf][0], v1 = facc[mf][nf][1];
            float v2 = facc[mf][nf][2], v3 = facc[mf][nf][3];
            if (r < NN) {
                *reinterpret_cast<float2*>(d_acc + (size_t)r * DD + n) = make_float2(v0, v1);
                s0 += v0; s1 += v1;
                q0 = fmaf(v0, v0, q0); q1 = fmaf(v1, v1, q1);
            }
            if (r + 8 < NN) {
                *reinterpret_cast<float2*>(d_acc + (size_t)(r + 8) * DD + n) = make_float2(v2, v3);
                s0 += v2; s1 += v3;
                q0 = fmaf(v2, v2, q0); q1 = fmaf(v3, v3, q1);
            }
        }
#pragma unroll
        for (int o = 4; o < 32; o <<= 1) {
            s0 += __shfl_xor_sync(0xFFFFFFFFu, s0, o);
            s1 += __shfl_xor_sync(0xFFFFFFFFu, s1, o);
            q0 += __shfl_xor_sync(0xFFFFFFFFu, q0, o);
            q1 += __shfl_xor_sync(0xFFFFFFFFu, q1, o);
        }
        if (lane < 4) {
            atomicAdd(stats + n, s0);
            atomicAdd(stats + n + 1, s1);
            atomicAdd(stats + DD + n, q0);
            atomicAdd(stats + DD + n + 1, q1);
        }
    }
}

// ======================= BatchNorm normalize (dual-write fp32 + tf32) =======================

__global__ void bn_norm_kernel(const float* __restrict__ gamma,
                               const float* __restrict__ beta,
                               float* __restrict__ outp, int write_out, int layer) {
    __shared__ float scale_s[DD];
    __shared__ float shift_s[DD];
    if (threadIdx.x < DD) {
        int c = threadIdx.x;
        const float* stats = d_stats3 + layer * 2 * DD;
        float mu = stats[c] * (1.0f / NN);
        float var = stats[DD + c] * (1.0f / NN) - mu * mu;
        float sc = __ldg(gamma + c) * rsqrtf(var + EPS);
        scale_s[c] = sc;
        shift_s[c] = __ldg(beta + c) - mu * sc;
    }
    __syncthreads();
    size_t i = (size_t)blockIdx.x * blockDim.x + threadIdx.x;
    if (i >= (size_t)NN * DD / 4) return;
    int col = (int)((i * 4) & (DD - 1));
    float4 v = reinterpret_cast<const float4*>(d_acc)[i];
    float4 o;
    o.x = v.x * scale_s[col + 0] + shift_s[col + 0];
    o.y = v.y * scale_s[col + 1] + shift_s[col + 1];
    o.z = v.z * scale_s[col + 2] + shift_s[col + 2];
    o.w = v.w * scale_s[col + 3] + shift_s[col + 3];
    if (write_out) {
        reinterpret_cast<float4*>(outp)[i] = o;
    } else {
        reinterpret_cast<float4*>(d_h)[i] = o;
        uint4 u;
        u.x = f2tf32(o.x); u.y = f2tf32(o.y); u.z = f2tf32(o.z); u.w = f2tf32(o.w);
        reinterpret_cast<uint4*>(d_hr)[i] = u;
    }
}

// ======================= launch =======================

extern "C" void kernel_launch(void* const* d_in, const int* in_sizes, int n_in,
                              void* d_out, int out_size) {
    const float* x     = (const float*)d_in[0];
    const int*   src   = (const int*)d_in[1];
    const int*   dst   = (const int*)d_in[2];
    const float* Ws    = (const float*)d_in[3];
    const float* Wn    = (const float*)d_in[4];
    const float* bias  = (const float*)d_in[5];
    const float* gamma = (const float*)d_in[6];
    const float* beta  = (const float*)d_in[7];
    float* out = (float*)d_out;

    cudaFuncSetAttribute(gemm_ca_kernel<false>,
                         cudaFuncAttributeMaxDynamicSharedMemorySize, SMEM_BYTES);
    cudaFuncSetAttribute(gemm_ca_kernel<true>,
                         cudaFuncAttributeMaxDynamicSharedMemorySize, SMEM_BYTES);

    {
        int n = NL * NET * 2 * DD * DD;
        wt_prep_kernel<<<(n + 255) / 256, 256>>>(Ws, Wn);
        xr_prep_kernel<<<(NN * 32 + 255) / 256, 256>>>(x);
    }
    {
        zero_cnt_kernel<<<(NROWS + 255) / 256, 256>>>();
        int ne = NET * NE;
        deg_count_kernel<<<(ne + 255) / 256, 256>>>(dst);
        scan1_kernel<<<SCAN_BLK, 256>>>();
        scan2_kernel<<<1, 512>>>();
        scan3_kernel<<<SCAN_BLK, 256>>>();
        permute_kernel<<<(ne + 255) / 256, 256>>>(src, dst);
    }

    const int gemm_blocks = (NN + 127) / 128;
    const int gather_blocks = (NROWS * 32 + 255) / 256;
    const int bn4_blocks = (NN * DD / 4 + 255) / 256;

    for (int l = 0; l < NL; l++) {
        int use_x = (l == 0);
        gather_kernel<<<gather_blocks, 256>>>(x, use_x);
        if (l == 2)
            gemm_ca_kernel<true><<<gemm_blocks, 256, SMEM_BYTES>>>(
                l, bias + (size_t)l * NET * DD, 0);
        else
            gemm_ca_kernel<false><<<gemm_blocks, 256, SMEM_BYTES>>>(
                l, bias + (size_t)l * NET * DD, 1);
        bn_norm_kernel<<<bn4_blocks, 256>>>(gamma + l * DD, beta + l * DD,
                                            out, (l == NL - 1), l);
    }
}

// round 17
// speedup vs baseline: 1.9969x; 1.0096x over previous
#include <cuda_runtime.h>
#include <cstdint>

#define NN 100000
#define NE 600000
#define NET 3
#define NL 3
#define DD 128
#define EPS 1e-5f
#define NROWS (NET * NN)
#define SCAN_BLK 293

// ---------------- static device scratch (device-code access ONLY) ----------------
__device__ float d_h[(size_t)NN * DD];                  // fp32 hidden (gather input)
__device__ float d_hr[(size_t)NN * DD];                 // tf32-rounded hidden (GEMM A input)
__device__ float d_neigh[(size_t)NET * NN * DD];        // tf32-rounded neighbor means
__device__ float d_acc[(size_t)NN * DD];
__device__ float d_invdeg[NROWS];
__device__ float d_stats3[NL * 2 * DD];
__device__ float d_Wt[(size_t)NL * NET * 2 * DD * DD];  // W^T tf32: [l][e][sel][n][kk]
__device__ int   d_cnt[NROWS];
__device__ int   d_rowoff[NROWS + 1];
__device__ int   d_bsums[512];
__device__ int   d_esrc[NET * NE];

// ======================= prep: CSR build =======================

__global__ void zero_cnt_kernel() {
    int i = blockIdx.x * blockDim.x + threadIdx.x;
    if (i < NROWS) d_cnt[i] = 0;
    if (i < NL * 2 * DD) d_stats3[i] = 0.f;
}
__global__ void deg_count_kernel(const int* __restrict__ dst) {
    int idx = blockIdx.x * blockDim.x + threadIdx.x;
    if (idx >= NET * NE) return;
    int k = idx / NE;
    atomicAdd(&d_cnt[k * NN + __ldg(dst + idx)], 1);
}
__global__ void scan1_kernel() {
    int base = blockIdx.x * 1024;
    int t = threadIdx.x;
    int sum = 0;
#pragma unroll
    for (int j = 0; j < 4; j++) {
        int i = base + t * 4 + j;
        if (i < NROWS) sum += d_cnt[i];
    }
#pragma unroll
    for (int o = 16; o; o >>= 1) sum += __shfl_down_sync(0xFFFFFFFFu, sum, o);
    __shared__ int ws[8];
    if ((t & 31) == 0) ws[t >> 5] = sum;
    __syncthreads();
    if (t == 0) {
        int v = 0;
#pragma unroll
        for (int i = 0; i < 8; i++) v += ws[i];
        d_bsums[blockIdx.x] = v;
    }
}
__global__ void scan2_kernel() {
    __shared__ int s[512];
    int t = threadIdx.x;
    int orig = (t < SCAN_BLK) ? d_bsums[t] : 0;
    s[t] = orig;
    __syncthreads();
#pragma unroll
    for (int o = 1; o < 512; o <<= 1) {
        int v = (t >= o) ? s[t - o] : 0;
        __syncthreads();
        s[t] += v;
        __syncthreads();
    }
    if (t < SCAN_BLK) d_bsums[t] = s[t] - orig;
}
__global__ void scan3_kernel() {
    int base = blockIdx.x * 1024;
    int t = threadIdx.x, lane = t & 31, warp = t >> 5;
    int vals[4];
    int tsum = 0;
#pragma unroll
    for (int j = 0; j < 4; j++) {
        int i = base + t * 4 + j;
        vals[j] = (i < NROWS) ? d_cnt[i] : 0;
        tsum += vals[j];
    }
    int inc = tsum;
#pragma unroll
    for (int o = 1; o < 32; o <<= 1) {
        int v = __shfl_up_sync(0xFFFFFFFFu, inc, o);
        if (lane >= o) inc += v;
    }
    int texcl = inc - tsum;
    __shared__ int wsum[8];
    if (lane == 31) wsum[warp] = inc;
    __syncthreads();
    __shared__ int woff[8];
    if (t == 0) {
        int a = 0;
#pragma unroll
        for (int i = 0; i < 8; i++) { woff[i] = a; a += wsum[i]; }
    }
    __syncthreads();
    int run = d_bsums[blockIdx.x] + woff[warp] + texcl;
#pragma unroll
    for (int j = 0; j < 4; j++) {
        int i = base + t * 4 + j;
        if (i < NROWS) {
            d_rowoff[i] = run;
            d_invdeg[i] = 1.0f / fmaxf((float)vals[j], 1.0f);
            d_cnt[i] = 0;
            run += vals[j];
        }
    }
    if (blockIdx.x == 0 && t == 0) d_rowoff[NROWS] = NET * NE;
}
__global__ void permute_kernel(const int* __restrict__ src, const int* __restrict__ dst) {
    int idx = blockIdx.x * blockDim.x + threadIdx.x;
    if (idx >= NET * NE) return;
    int k = idx / NE;
    int g = k * NN + __ldg(dst + idx);
    int pos = d_rowoff[g] + atomicAdd(&d_cnt[g], 1);
    d_esrc[pos] = __ldg(src + idx);
}

__device__ __forceinline__ uint32_t f2tf32(float x) {
    uint32_t r;
    asm("cvt.rna.tf32.f32 %0, %1;" : "=r"(r) : "f"(x));
    return r;
}

// W^T + tf32; layer-2 (m==6) self slot holds merged sum_e(Ws_e) (last layer has no relu)
__global__ void wt_prep_kernel(const float* __restrict__ Ws, const float* __restrict__ Wn) {
    int i = blockIdx.x * blockDim.x + threadIdx.x;
    if (i >= NL * NET * 2 * DD * DD) return;
    int kk = i & 127;
    int n = (i >> 7) & 127;
    int sel = (i >> 14) & 1;
    int m = i >> 15;
    float v;
    if (m == 2 * NET && sel == 0) {
        v = __ldg(Ws + (size_t)6 * 16384 + kk * DD + n)
          + __ldg(Ws + (size_t)7 * 16384 + kk * DD + n)
          + __ldg(Ws + (size_t)8 * 16384 + kk * DD + n);
    } else {
        v = __ldg((sel ? Wn : Ws) + (size_t)m * 16384 + kk * DD + n);
    }
    d_Wt[i] = __uint_as_float(f2tf32(v));
}

// x -> tf32-rounded d_hr (layer-0 GEMM A source)
__global__ void xr_prep_kernel(const float* __restrict__ x) {
    int i = blockIdx.x * blockDim.x + threadIdx.x;
    if (i >= NN * 32) return;
    float4 v = __ldg(reinterpret_cast<const float4*>(x) + i);
    uint4 u;
    u.x = f2tf32(v.x); u.y = f2tf32(v.y); u.z = f2tf32(v.z); u.w = f2tf32(v.w);
    reinterpret_cast<uint4*>(d_hr)[i] = u;
}

// ======================= gather (CSR mean; output tf32-rounded) =======================
__global__ void gather_kernel(const float* __restrict__ x, int use_x) {
    const float* hin = use_x ? x : d_h;
    int w = (blockIdx.x * blockDim.x + threadIdx.x) >> 5;
    int lane = threadIdx.x & 31;
    if (w >= NROWS) return;
    int o0 = __ldg(&d_rowoff[w]);
    int o1 = __ldg(&d_rowoff[w + 1]);
    float4 a = make_float4(0.f, 0.f, 0.f, 0.f);
    int s = (o0 < o1) ? __ldg(&d_esrc[o0]) : 0;
    for (int e = o0; e < o1; e++) {
        int sn = (e + 1 < o1) ? __ldg(&d_esrc[e + 1]) : 0;
        float4 v = __ldg(reinterpret_cast<const float4*>(hin + (size_t)s * DD) + lane);
        a.x += v.x; a.y += v.y; a.z += v.z; a.w += v.w;
        s = sn;
    }
    float sc = d_invdeg[w];
    uint4 u;
    u.x = f2tf32(a.x * sc); u.y = f2tf32(a.y * sc);
    u.z = f2tf32(a.z * sc); u.w = f2tf32(a.w * sc);
    reinterpret_cast<uint4*>(d_neigh)[(size_t)w * 32 + lane] = u;
}

// ======================= cp.async 4-stage tf32 mma GEMM =======================

#define ASTRIDE 36
#define ATILE (128 * ASTRIDE)
#define NSTAGE 4
#define SMEM_BYTES (2 * NSTAGE * ATILE * 4)   // 147456 B

__device__ __forceinline__ void ldsm4(uint32_t* r, uint32_t addr) {
    asm volatile("ldmatrix.sync.aligned.m8n8.x4.shared.b16 {%0,%1,%2,%3}, [%4];"
                 : "=r"(r[0]), "=r"(r[1]), "=r"(r[2]), "=r"(r[3]) : "r"(addr));
}
__device__ __forceinline__ void mma8(float* c, const uint32_t* a, uint32_t b0, uint32_t b1) {
    asm volatile("mma.sync.aligned.m16n8k8.row.col.f32.tf32.tf32.f32 "
                 "{%0,%1,%2,%3}, {%4,%5,%6,%7}, {%8,%9}, {%0,%1,%2,%3};"
                 : "+f"(c[0]), "+f"(c[1]), "+f"(c[2]), "+f"(c[3])
                 : "r"(a[0]), "r"(a[1]), "r"(a[2]), "r"(a[3]), "r"(b0), "r"(b1));
}
__device__ __forceinline__ void cpa16(uint32_t dst, const float* src, int nbytes) {
    asm volatile("cp.async.cg.shared.global [%0], [%1], 16, %2;"
                 :: "r"(dst), "l"(src), "r"(nbytes));
}
#define CP_COMMIT() asm volatile("cp.async.commit_group;" ::: "memory")
#define CP_WAIT2()  asm volatile("cp.async.wait_group 2;" ::: "memory")

// issue one 128x32 A tile (row-bounded) + one 128x32 B tile via cp.async
__device__ __forceinline__ void issue_tile(uint32_t a_u, uint32_t b_u,
                                           const float* __restrict__ Asrc, int m0, int koff,
                                           const float* __restrict__ W, int tid) {
#pragma unroll
    for (int i = 0; i < 4; i++) {
        int c = tid + i * 256;          // 0..1023
        int row = c >> 3, q = c & 7;
        int gr = m0 + row;
        cpa16(a_u + (uint32_t)(row * ASTRIDE + q * 4) * 4,
              Asrc + (size_t)gr * DD + koff + q * 4, (gr < NN) ? 16 : 0);
    }
#pragma unroll
    for (int i = 0; i < 4; i++) {
        int c = tid + i * 256;
        int row = c >> 3, q = c & 7;
        cpa16(b_u + (uint32_t)(row * ASTRIDE + q * 4) * 4,
              W + (size_t)row * DD + koff + q * 4, 16);
    }
}

template<bool MERGED>
__global__ void __launch_bounds__(256)
gemm_ca_kernel(int layer, const float* __restrict__ bias, int do_relu) {
    extern __shared__ float sm[];
    uint32_t smb = (uint32_t)__cvta_generic_to_shared(sm);
    uint32_t asu[NSTAGE], bsu[NSTAGE];
#pragma unroll
    for (int s = 0; s < NSTAGE; s++) {
        asu[s] = smb + (uint32_t)s * ATILE * 4;
        bsu[s] = smb + (uint32_t)(NSTAGE + s) * ATILE * 4;
    }

    const float* Wl = d_Wt + (size_t)layer * NET * 2 * DD * DD;
    float* stats = d_stats3 + layer * 2 * DD;
    constexpr int NT = MERGED ? 16 : 24;

    int tid = threadIdx.x, lane = tid & 31, wid = tid >> 5;
    int wm = wid & 3, wn = wid >> 2;
    int m0 = blockIdx.x * 128;

    uint32_t aoffb[2];
#pragma unroll
    for (int mf = 0; mf < 2; mf++)
        aoffb[mf] = ((wm * 32 + mf * 16 + (lane & 15)) * ASTRIDE + (lane >> 4) * 4) * 4;
    uint32_t boffb[4];
#pragma unroll
    for (int nf2 = 0; nf2 < 4; nf2++) {
        int n = wn * 64 + nf2 * 16 + (lane & 7) + ((lane >> 4) << 3);
        boffb[nf2] = (n * ASTRIDE + ((lane >> 3) & 1) * 4) * 4;
    }

    float facc[2][8][4], acc[2][8][4];
#pragma unroll
    for (int i = 0; i < 2; i++)
#pragma unroll
        for (int j = 0; j < 8; j++)
#pragma unroll
            for (int e = 0; e < 4; e++) { facc[i][j][e] = 0.f; acc[i][j][e] = 0.f; }

    // ---- prologue: issue tiles 0..2 ----
#pragma unroll
    for (int t = 0; t < NSTAGE - 1; t++) {
        const float* A;
        const float* W;
        if (!MERGED) {
            const int pn = t >> 2;
            A = (pn & 1) ? (d_neigh + (size_t)(pn >> 1) * NN * DD) : d_hr;
            W = Wl + (size_t)pn * 16384;
        } else {
            const int p = t >> 2;
            A = (p == 0) ? d_hr : (d_neigh + (size_t)(p - 1) * NN * DD);
            W = (p == 0) ? Wl : (Wl + (size_t)((p - 1) * 2 + 1) * 16384);
        }
        issue_tile(asu[t], bsu[t], A, m0, (t & 3) * 32, W, tid);
        CP_COMMIT();
    }

#pragma unroll
    for (int t = 0; t < NT; t++) {
        const int cur = t & (NSTAGE - 1);
        CP_WAIT2();
        __syncthreads();   // tile t visible; all warps done with tile t-1's buffer
        {
            const int tn = t + NSTAGE - 1;
            if (tn < NT) {
                const float* A;
                const float* W;
                if (!MERGED) {
                    const int pn = tn >> 2;
                    A = (pn & 1) ? (d_neigh + (size_t)(pn >> 1) * NN * DD) : d_hr;
                    W = Wl + (size_t)pn * 16384;
                } else {
                    const int p = tn >> 2;
                    A = (p == 0) ? d_hr : (d_neigh + (size_t)(p - 1) * NN * DD);
                    W = (p == 0) ? Wl : (Wl + (size_t)((p - 1) * 2 + 1) * 16384);
                }
                issue_tile(asu[tn & (NSTAGE - 1)], bsu[tn & (NSTAGE - 1)],
                           A, m0, (tn & 3) * 32, W, tid);
            }
            CP_COMMIT();   // always commit (possibly empty) to keep group count uniform
        }
#pragma unroll
        for (int ks = 0; ks < 4; ks++) {
            uint32_t af[2][4];
            ldsm4(af[0], asu[cur] + aoffb[0] + ks * 32);
            ldsm4(af[1], asu[cur] + aoffb[1] + ks * 32);
            uint32_t bf[4][4];
#pragma unroll
            for (int nf2 = 0; nf2 < 4; nf2++)
                ldsm4(bf[nf2], bsu[cur] + boffb[nf2] + ks * 32);
#pragma unroll
            for (int mf = 0; mf < 2; mf++)
#pragma unroll
                for (int nf = 0; nf < 8; nf++) {
                    int q = (nf & 1) * 2;
                    mma8(acc[mf][nf], af[mf], bf[nf >> 1][q], bf[nf >> 1][q + 1]);
                }
        }
        const bool fold = MERGED ? (t == NT - 1) : ((t & 7) == 7);
        if (fold) {
#pragma unroll
            for (int nf = 0; nf < 8; nf++) {
                int n = wn * 64 + nf * 8 + ((lane & 3) << 1);
                float b0, b1;
                if (MERGED) {
                    b0 = __ldg(bias + n) + __ldg(bias + DD + n) + __ldg(bias + 2 * DD + n);
                    b1 = __ldg(bias + n + 1) + __ldg(bias + DD + n + 1) + __ldg(bias + 2 * DD + n + 1);
                } else {
                    const float* be = bias + (t >> 3) * DD;
                    b0 = __ldg(be + n); b1 = __ldg(be + n + 1);
                }
#pragma unroll
                for (int mf = 0; mf < 2; mf++) {
                    float v0 = acc[mf][nf][0] + b0, v1 = acc[mf][nf][1] + b1;
                    float v2 = acc[mf][nf][2] + b0, v3 = acc[mf][nf][3] + b1;
                    if (do_relu) {
                        v0 = fmaxf(v0, 0.f); v1 = fmaxf(v1, 0.f);
                        v2 = fmaxf(v2, 0.f); v3 = fmaxf(v3, 0.f);
                    }
                    facc[mf][nf][0] += v0; facc[mf][nf][1] += v1;
                    facc[mf][nf][2] += v2; facc[mf][nf][3] += v3;
                    acc[mf][nf][0] = 0.f; acc[mf][nf][1] = 0.f;
                    acc[mf][nf][2] = 0.f; acc[mf][nf][3] = 0.f;
                }
            }
        }
    }

    // ---- epilogue: store + BN column stats ----
    int r0 = m0 + wm * 32 + (lane >> 2);
    int rr[2] = { r0, r0 + 16 };
#pragma unroll
    for (int nf = 0; nf < 8; nf++) {
        int n = wn * 64 + nf * 8 + ((lane & 3) << 1);
        float s0 = 0.f, s1 = 0.f, q0 = 0.f, q1 = 0.f;
#pragma unroll
        for (int mf = 0; mf < 2; mf++) {
            int r = rr[mf];
            float v0 = facc[mf][nf][0], v1 = facc[mf][nf][1];
            float v2 = facc[mf][nf][2], v3 = facc[mf][nf][3];
            if (r < NN) {
                *reinterpret_cast<float2*>(d_acc + (size_t)r * DD + n) = make_float2(v0, v1);
                s0 += v0; s1 += v1;
                q0 = fmaf(v0, v0, q0); q1 = fmaf(v1, v1, q1);
            }
            if (r + 8 < NN) {
                *reinterpret_cast<float2*>(d_acc + (size_t)(r + 8) * DD + n) = make_float2(v2, v3);
                s0 += v2; s1 += v3;
                q0 = fmaf(v2, v2, q0); q1 = fmaf(v3, v3, q1);
            }
        }
#pragma unroll
        for (int o = 4; o < 32; o <<= 1) {
            s0 += __shfl_xor_sync(0xFFFFFFFFu, s0, o);
            s1 += __shfl_xor_sync(0xFFFFFFFFu, s1, o);
            q0 += __shfl_xor_sync(0xFFFFFFFFu, q0, o);
            q1 += __shfl_xor_sync(0xFFFFFFFFu, q1, o);
        }
        if (lane < 4) {
            atomicAdd(stats + n, s0);
            atomicAdd(stats + n + 1, s1);
            atomicAdd(stats + DD + n, q0);
            atomicAdd(stats + DD + n + 1, q1);
        }
    }
}

// ======================= BatchNorm normalize (dual-write fp32 + tf32) =======================

__global__ void bn_norm_kernel(const float* __restrict__ gamma,
                               const float* __restrict__ beta,
                               float* __restrict__ outp, int write_out, int layer) {
    __shared__ float scale_s[DD];
    __shared__ float shift_s[DD];
    if (threadIdx.x < DD) {
        int c = threadIdx.x;
        const float* stats = d_stats3 + layer * 2 * DD;
        float mu = stats[c] * (1.0f / NN);
        float var = stats[DD + c] * (1.0f / NN) - mu * mu;
        float sc = __ldg(gamma + c) * rsqrtf(var + EPS);
        scale_s[c] = sc;
        shift_s[c] = __ldg(beta + c) - mu * sc;
    }
    __syncthreads();
    size_t i = (size_t)blockIdx.x * blockDim.x + threadIdx.x;
    if (i >= (size_t)NN * DD / 4) return;
    int col = (int)((i * 4) & (DD - 1));
    float4 v = reinterpret_cast<const float4*>(d_acc)[i];
    float4 o;
    o.x = v.x * scale_s[col + 0] + shift_s[col + 0];
    o.y = v.y * scale_s[col + 1] + shift_s[col + 1];
    o.z = v.z * scale_s[col + 2] + shift_s[col + 2];
    o.w = v.w * scale_s[col + 3] + shift_s[col + 3];
    if (write_out) {
        reinterpret_cast<float4*>(outp)[i] = o;
    } else {
        reinterpret_cast<float4*>(d_h)[i] = o;
        uint4 u;
        u.x = f2tf32(o.x); u.y = f2tf32(o.y); u.z = f2tf32(o.z); u.w = f2tf32(o.w);
        reinterpret_cast<uint4*>(d_hr)[i] = u;
    }
}

// ======================= launch =======================

extern "C" void kernel_launch(void* const* d_in, const int* in_sizes, int n_in,
                              void* d_out, int out_size) {
    const float* x     = (const float*)d_in[0];
    const int*   src   = (const int*)d_in[1];
    const int*   dst   = (const int*)d_in[2];
    const float* Ws    = (const float*)d_in[3];
    const float* Wn    = (const float*)d_in[4];
    const float* bias  = (const float*)d_in[5];
    const float* gamma = (const float*)d_in[6];
    const float* beta  = (const float*)d_in[7];
    float* out = (float*)d_out;

    cudaFuncSetAttribute(gemm_ca_kernel<false>,
                         cudaFuncAttributeMaxDynamicSharedMemorySize, SMEM_BYTES);
    cudaFuncSetAttribute(gemm_ca_kernel<true>,
                         cudaFuncAttributeMaxDynamicSharedMemorySize, SMEM_BYTES);

    {
        int n = NL * NET * 2 * DD * DD;
        wt_prep_kernel<<<(n + 255) / 256, 256>>>(Ws, Wn);
        xr_prep_kernel<<<(NN * 32 + 255) / 256, 256>>>(x);
    }
    {
        zero_cnt_kernel<<<(NROWS + 255) / 256, 256>>>();
        int ne = NET * NE;
        deg_count_kernel<<<(ne + 255) / 256, 256>>>(dst);
        scan1_kernel<<<SCAN_BLK, 256>>>();
        scan2_kernel<<<1, 512>>>();
        scan3_kernel<<<SCAN_BLK, 256>>>();
        permute_kernel<<<(ne + 255) / 256, 256>>>(src, dst);
    }

    const int gemm_blocks = (NN + 127) / 128;
    const int gather_blocks = (NROWS * 32 + 255) / 256;
    const int bn4_blocks = (NN * DD / 4 + 255) / 256;

    for (int l = 0; l < NL; l++) {
        int use_x = (l == 0);
        gather_kernel<<<gather_blocks, 256>>>(x, use_x);
        if (l == 2)
            gemm_ca_kernel<true><<<gemm_blocks, 256, SMEM_BYTES>>>(
                l, bias + (size_t)l * NET * DD, 0);
        else
            gemm_ca_kernel<false><<<gemm_blocks, 256, SMEM_BYTES>>>(
                l, bias + (size_t)l * NET * DD, 1);
        bn_norm_kernel<<<bn4_blocks, 256>>>(gamma + l * DD, beta + l * DD,
                                            out, (l == NL - 1), l);
    }
}